// round 6
// baseline (speedup 1.0000x reference)
#include <cuda_runtime.h>
#include <cuda_fp16.h>
#include <cuda_bf16.h>
#include <cstdint>

#define NN 100000
#define NE 1600000
#define NTOT (NE + NN)

// ---------------- scratch (device globals: allocation-free) ----------------
__device__ float  g_bufA[NN * 160];
__device__ float  g_bufB[NN * 160];
__device__ __half g_bufH[NN * 80];
__device__ int    g_cnt[NN];
__device__ float  g_dis[NN];
__device__ int    g_rowptr[NN + 1];
__device__ int    g_fill[NN];
__device__ int2   g_entries[NTOT];   // {src_node, float_bits(norm)} sorted by dst
__device__ int    g_bsums[128];

static inline int cdiv(int a, int b) { return (a + b - 1) / b; }

// ---------------- CSR build ----------------
__global__ void k_init_cnt() {
    int i = blockIdx.x * blockDim.x + threadIdx.x;
    if (i < NN) g_cnt[i] = 1;   // self-loop
}
__global__ void k_count(const int* __restrict__ dst) {
    int e = blockIdx.x * blockDim.x + threadIdx.x;
    if (e < NE) atomicAdd(&g_cnt[dst[e]], 1);
}
__global__ void k_scan1() {   // also computes g_dis
    __shared__ int s[1024];
    int i = blockIdx.x * 1024 + threadIdx.x;
    int v = (i < NN) ? g_cnt[i] : 0;
    if (i < NN) g_dis[i] = rsqrtf((float)v);
    s[threadIdx.x] = v;
    __syncthreads();
    for (int d = 1; d < 1024; d <<= 1) {
        int t = (threadIdx.x >= d) ? s[threadIdx.x - d] : 0;
        __syncthreads();
        s[threadIdx.x] += t;
        __syncthreads();
    }
    if (i < NN) g_rowptr[i + 1] = s[threadIdx.x];
    if (threadIdx.x == 1023) g_bsums[blockIdx.x] = s[1023];
}
__global__ void k_scan2(int nb) {
    __shared__ int s[128];
    int v = (threadIdx.x < nb) ? g_bsums[threadIdx.x] : 0;
    s[threadIdx.x] = v;
    __syncthreads();
    for (int d = 1; d < 128; d <<= 1) {
        int t = (threadIdx.x >= d) ? s[threadIdx.x - d] : 0;
        __syncthreads();
        s[threadIdx.x] += t;
        __syncthreads();
    }
    if (threadIdx.x < nb) g_bsums[threadIdx.x] = s[threadIdx.x] - v;
}
__global__ void k_scan3() {
    int i = blockIdx.x * 1024 + threadIdx.x;
    if (i < NN) g_rowptr[i + 1] += g_bsums[blockIdx.x];
    if (i == 0) g_rowptr[0] = 0;
}
__global__ void k_self() {
    int i = blockIdx.x * blockDim.x + threadIdx.x;
    if (i < NN) {
        int p = g_rowptr[i];
        float d = g_dis[i];
        g_entries[p] = make_int2(i, __float_as_int(d * d));
        g_fill[i] = p + 1;
    }
}
__global__ void k_edges(const int* __restrict__ src, const int* __restrict__ dst) {
    int e = blockIdx.x * blockDim.x + threadIdx.x;
    if (e < NE) {
        int s = src[e], d = dst[e];
        int p = atomicAdd(&g_fill[d], 1);
        g_entries[p] = make_int2(s, __float_as_int(g_dis[s] * g_dis[d]));
    }
}

// ---------------- scalar aggregation (C=3), unroll-4 ----------------
template <int ACT, bool BIAS>
__global__ void k_agg3(const float* __restrict__ in, const float* __restrict__ bias,
                       float* __restrict__ out) {
    int gwarp = (blockIdx.x * blockDim.x + threadIdx.x) >> 5;
    int lane = threadIdx.x & 31;
    int node = gwarp * 8 + lane / 4;
    int cl = lane & 3;
    if (node >= NN) return;
    int p0 = g_rowptr[node], p1 = g_rowptr[node + 1];
    float acc = 0.f;
    bool act3 = (cl < 3);
    int p = p0;
    for (; p + 4 <= p1; p += 4) {
        int2 e0 = __ldg(&g_entries[p]);
        int2 e1 = __ldg(&g_entries[p + 1]);
        int2 e2 = __ldg(&g_entries[p + 2]);
        int2 e3 = __ldg(&g_entries[p + 3]);
        if (act3) {
            float v0 = __ldg(in + (long)e0.x * 3 + cl);
            float v1 = __ldg(in + (long)e1.x * 3 + cl);
            float v2 = __ldg(in + (long)e2.x * 3 + cl);
            float v3 = __ldg(in + (long)e3.x * 3 + cl);
            acc = fmaf(__int_as_float(e0.y), v0, acc);
            acc = fmaf(__int_as_float(e1.y), v1, acc);
            acc = fmaf(__int_as_float(e2.y), v2, acc);
            acc = fmaf(__int_as_float(e3.y), v3, acc);
        }
    }
    for (; p < p1; p++) {
        int2 e = __ldg(&g_entries[p]);
        if (act3) {
            float v = __ldg(in + (long)e.x * 3 + cl);
            acc = fmaf(__int_as_float(e.y), v, acc);
        }
    }
    if (act3) {
        float v = acc;
        if (BIAS) v += bias[cl];
        if (ACT == 1) v = fmaxf(v, 0.f);
        if (ACT == 2) v = tanhf(v);
        out[(long)node * 3 + cl] = v;
    }
}

// ---------------- fp32 vectorized aggregation (C % 4 == 0), unroll-4 ----------------
template <int C, int SUB, int ACT, bool BIAS>
__global__ void k_aggv(const float* __restrict__ in, const float* __restrict__ bias,
                       float* __restrict__ out) {
    constexpr int NV = C / 4;
    static_assert(NV <= SUB, "SUB too small");
    const int nodesPerWarp = 32 / SUB;
    int gwarp = (blockIdx.x * blockDim.x + threadIdx.x) >> 5;
    int lane = threadIdx.x & 31;
    int node = gwarp * nodesPerWarp + lane / SUB;
    int vl = lane % SUB;
    if (node >= NN) return;
    int p0 = g_rowptr[node], p1 = g_rowptr[node + 1];
    float4 acc = make_float4(0.f, 0.f, 0.f, 0.f);
    bool active = (vl < NV);
    int p = p0;
    for (; p + 4 <= p1; p += 4) {
        int2 e0 = __ldg(&g_entries[p]);
        int2 e1 = __ldg(&g_entries[p + 1]);
        int2 e2 = __ldg(&g_entries[p + 2]);
        int2 e3 = __ldg(&g_entries[p + 3]);
        if (active) {
            float4 v0 = __ldg((const float4*)(in + (long)e0.x * C) + vl);
            float4 v1 = __ldg((const float4*)(in + (long)e1.x * C) + vl);
            float4 v2 = __ldg((const float4*)(in + (long)e2.x * C) + vl);
            float4 v3 = __ldg((const float4*)(in + (long)e3.x * C) + vl);
            float w0 = __int_as_float(e0.y), w1 = __int_as_float(e1.y);
            float w2 = __int_as_float(e2.y), w3 = __int_as_float(e3.y);
            acc.x = fmaf(w0, v0.x, acc.x); acc.y = fmaf(w0, v0.y, acc.y);
            acc.z = fmaf(w0, v0.z, acc.z); acc.w = fmaf(w0, v0.w, acc.w);
            acc.x = fmaf(w1, v1.x, acc.x); acc.y = fmaf(w1, v1.y, acc.y);
            acc.z = fmaf(w1, v1.z, acc.z); acc.w = fmaf(w1, v1.w, acc.w);
            acc.x = fmaf(w2, v2.x, acc.x); acc.y = fmaf(w2, v2.y, acc.y);
            acc.z = fmaf(w2, v2.z, acc.z); acc.w = fmaf(w2, v2.w, acc.w);
            acc.x = fmaf(w3, v3.x, acc.x); acc.y = fmaf(w3, v3.y, acc.y);
            acc.z = fmaf(w3, v3.z, acc.z); acc.w = fmaf(w3, v3.w, acc.w);
        }
    }
    for (; p < p1; p++) {
        int2 e = __ldg(&g_entries[p]);
        if (active) {
            float w = __int_as_float(e.y);
            float4 v = __ldg((const float4*)(in + (long)e.x * C) + vl);
            acc.x = fmaf(w, v.x, acc.x); acc.y = fmaf(w, v.y, acc.y);
            acc.z = fmaf(w, v.z, acc.z); acc.w = fmaf(w, v.w, acc.w);
        }
    }
    if (active) {
        if (BIAS) {
            float4 bv = __ldg((const float4*)bias + vl);
            acc.x += bv.x; acc.y += bv.y; acc.z += bv.z; acc.w += bv.w;
        }
        if (ACT == 1) {
            acc.x = fmaxf(acc.x, 0.f); acc.y = fmaxf(acc.y, 0.f);
            acc.z = fmaxf(acc.z, 0.f); acc.w = fmaxf(acc.w, 0.f);
        }
        *((float4*)(out + (long)node * C) + vl) = acc;
    }
}

// ---------------- fp16-input aggregation (C % 8 == 0), int4 loads, unroll-4 ----------------
__device__ __forceinline__ void accum8h(float* acc, int4 h, float w) {
    const __half2* hp = (const __half2*)&h;
#pragma unroll
    for (int i = 0; i < 4; i++) {
        float2 f = __half22float2(hp[i]);
        acc[2 * i]     = fmaf(w, f.x, acc[2 * i]);
        acc[2 * i + 1] = fmaf(w, f.y, acc[2 * i + 1]);
    }
}

template <int C, int SUB, int ACT, bool BIAS>
__global__ void k_aggvh(const __half* __restrict__ in, const float* __restrict__ bias,
                        float* __restrict__ out) {
    constexpr int NV = C / 8;
    static_assert(NV <= SUB, "SUB too small");
    const int nodesPerWarp = 32 / SUB;
    int gwarp = (blockIdx.x * blockDim.x + threadIdx.x) >> 5;
    int lane = threadIdx.x & 31;
    int node = gwarp * nodesPerWarp + lane / SUB;
    int vl = lane % SUB;
    if (node >= NN) return;
    int p0 = g_rowptr[node], p1 = g_rowptr[node + 1];
    float acc[8] = {};
    bool active = (vl < NV);
    int p = p0;
    for (; p + 4 <= p1; p += 4) {
        int2 e0 = __ldg(&g_entries[p]);
        int2 e1 = __ldg(&g_entries[p + 1]);
        int2 e2 = __ldg(&g_entries[p + 2]);
        int2 e3 = __ldg(&g_entries[p + 3]);
        if (active) {
            int4 h0 = __ldg((const int4*)(in + (long)e0.x * C) + vl);
            int4 h1 = __ldg((const int4*)(in + (long)e1.x * C) + vl);
            int4 h2 = __ldg((const int4*)(in + (long)e2.x * C) + vl);
            int4 h3 = __ldg((const int4*)(in + (long)e3.x * C) + vl);
            accum8h(acc, h0, __int_as_float(e0.y));
            accum8h(acc, h1, __int_as_float(e1.y));
            accum8h(acc, h2, __int_as_float(e2.y));
            accum8h(acc, h3, __int_as_float(e3.y));
        }
    }
    for (; p < p1; p++) {
        int2 e = __ldg(&g_entries[p]);
        if (active) {
            int4 h = __ldg((const int4*)(in + (long)e.x * C) + vl);
            accum8h(acc, h, __int_as_float(e.y));
        }
    }
    if (active) {
        if (BIAS) {
            const float4* bp = (const float4*)bias + vl * 2;
            float4 b0 = __ldg(bp), b1 = __ldg(bp + 1);
            acc[0] += b0.x; acc[1] += b0.y; acc[2] += b0.z; acc[3] += b0.w;
            acc[4] += b1.x; acc[5] += b1.y; acc[6] += b1.z; acc[7] += b1.w;
        }
        if (ACT == 1) {
#pragma unroll
            for (int i = 0; i < 8; i++) acc[i] = fmaxf(acc[i], 0.f);
        }
        float4* op = (float4*)(out + (long)node * C) + vl * 2;
        op[0] = make_float4(acc[0], acc[1], acc[2], acc[3]);
        op[1] = make_float4(acc[4], acc[5], acc[6], acc[7]);
    }
}

// ---------------- fused eg1: out = relu(agg(x, C=3) @ W(3x160) + b) ----------------
__global__ void __launch_bounds__(256)
k_eg1(const float* __restrict__ x, const float* __restrict__ W,
      const float* __restrict__ Bb, float* __restrict__ out) {
    __shared__ float sW[480];
    __shared__ float sB[160];
    for (int i = threadIdx.x; i < 480; i += 256) sW[i] = W[i];
    for (int i = threadIdx.x; i < 160; i += 256) sB[i] = Bb[i];
    __syncthreads();
    int gwarp = (blockIdx.x * blockDim.x + threadIdx.x) >> 5;
    int lane = threadIdx.x & 31;
    int nodeBase = gwarp * 8;
    int node = nodeBase + lane / 4;
    int cl = lane & 3;
    float acc = 0.f;
    if (node < NN) {
        int p0 = g_rowptr[node], p1 = g_rowptr[node + 1];
        bool act3 = (cl < 3);
        int p = p0;
        for (; p + 4 <= p1; p += 4) {
            int2 e0 = __ldg(&g_entries[p]);
            int2 e1 = __ldg(&g_entries[p + 1]);
            int2 e2 = __ldg(&g_entries[p + 2]);
            int2 e3 = __ldg(&g_entries[p + 3]);
            if (act3) {
                float v0 = __ldg(x + (long)e0.x * 3 + cl);
                float v1 = __ldg(x + (long)e1.x * 3 + cl);
                float v2 = __ldg(x + (long)e2.x * 3 + cl);
                float v3 = __ldg(x + (long)e3.x * 3 + cl);
                acc = fmaf(__int_as_float(e0.y), v0, acc);
                acc = fmaf(__int_as_float(e1.y), v1, acc);
                acc = fmaf(__int_as_float(e2.y), v2, acc);
                acc = fmaf(__int_as_float(e3.y), v3, acc);
            }
        }
        for (; p < p1; p++) {
            int2 e = __ldg(&g_entries[p]);
            if (act3) {
                float v = __ldg(x + (long)e.x * 3 + cl);
                acc = fmaf(__int_as_float(e.y), v, acc);
            }
        }
    }
#pragma unroll
    for (int j = 0; j < 8; j++) {
        int n2 = nodeBase + j;
        float a0 = __shfl_sync(0xffffffffu, acc, j * 4 + 0);
        float a1 = __shfl_sync(0xffffffffu, acc, j * 4 + 1);
        float a2 = __shfl_sync(0xffffffffu, acc, j * 4 + 2);
        if (n2 >= NN) break;
        float* op = out + (long)n2 * 160;
#pragma unroll
        for (int c0 = 0; c0 < 160; c0 += 32) {
            int c = c0 + lane;
            float v = sB[c];
            v = fmaf(a0, sW[c], v);
            v = fmaf(a1, sW[160 + c], v);
            v = fmaf(a2, sW[320 + c], v);
            op[c] = fmaxf(v, 0.f);
        }
    }
}

// ---------------- thread-per-node dense ----------------
template <int K, int NC, int ACT, bool BIAS, bool OUTH>
__global__ void __launch_bounds__(256)
k_dense(const float* __restrict__ in, const float* __restrict__ W,
        const float* __restrict__ bias, void* __restrict__ outv) {
    __shared__ float sW[K * NC];
    __shared__ float sB[NC];
    for (int i = threadIdx.x; i < K * NC; i += 256) sW[i] = W[i];
    if (BIAS) for (int i = threadIdx.x; i < NC; i += 256) sB[i] = bias[i];
    __syncthreads();
    int n = blockIdx.x * blockDim.x + threadIdx.x;
    if (n >= NN) return;
    float acc[NC];
#pragma unroll
    for (int c = 0; c < NC; c++) acc[c] = BIAS ? sB[c] : 0.f;
    const float4* ip = (const float4*)(in + (long)n * K);
#pragma unroll
    for (int k4 = 0; k4 < K / 4; k4++) {
        float4 v = __ldg(ip + k4);
#pragma unroll
        for (int c = 0; c < NC; c++) {
            acc[c] = fmaf(v.x, sW[(k4 * 4 + 0) * NC + c], acc[c]);
            acc[c] = fmaf(v.y, sW[(k4 * 4 + 1) * NC + c], acc[c]);
            acc[c] = fmaf(v.z, sW[(k4 * 4 + 2) * NC + c], acc[c]);
            acc[c] = fmaf(v.w, sW[(k4 * 4 + 3) * NC + c], acc[c]);
        }
    }
#pragma unroll
    for (int c = 0; c < NC; c++) {
        float v = acc[c];
        if (ACT == 1) v = fmaxf(v, 0.f);
        if (OUTH) ((__half*)outv)[(long)n * NC + c] = __float2half_rn(v);
        else ((float*)outv)[(long)n * NC + c] = v;
    }
}

// ---------------- fp16-split tensor-core GEMM (3-pass, fp32 accuracy) ----------------
__device__ __forceinline__ void mma_f16(float* c, uint32_t a0, uint32_t a1,
                                        uint32_t a2, uint32_t a3,
                                        uint32_t b0, uint32_t b1) {
    asm volatile(
        "mma.sync.aligned.m16n8k16.row.col.f32.f16.f16.f32 "
        "{%0,%1,%2,%3}, {%4,%5,%6,%7}, {%8,%9}, {%0,%1,%2,%3};\n"
        : "+f"(c[0]), "+f"(c[1]), "+f"(c[2]), "+f"(c[3])
        : "r"(a0), "r"(a1), "r"(a2), "r"(a3), "r"(b0), "r"(b1));
}

#define HBM_T 128   // tile M
#define HBN_T 80    // tile N
#define HBK_T 32    // tile K
#define HSA 40      // A smem stride in halves (conflict-free)
#define HSB 40      // B smem stride in halves (conflict-free)

template <int ACT, bool BIAS, bool OUTH>
__global__ void __launch_bounds__(256)
k_gemm_f16(const float* __restrict__ A, const float* __restrict__ W,
           const float* __restrict__ bias, void* __restrict__ outv,
           int M, int K, int Nc) {
    __shared__ __half sAh[HBM_T * HSA];
    __shared__ __half sAl[HBM_T * HSA];
    __shared__ __half sBh[HBN_T * HSB];   // transposed: [n][k]
    __shared__ __half sBl[HBN_T * HSB];

    int tid = threadIdx.x;
    int wid = tid >> 5;
    int lane = tid & 31;
    int g = lane >> 2;
    int t = lane & 3;
    int wm = wid & 3;
    int wn = wid >> 2;
    int row0 = blockIdx.y * HBM_T;
    int col0 = blockIdx.x * HBN_T;

    float acc[2][5][4];
#pragma unroll
    for (int i = 0; i < 2; i++)
#pragma unroll
        for (int j = 0; j < 5; j++)
#pragma unroll
            for (int q = 0; q < 4; q++) acc[i][j][q] = 0.f;

    for (int k0 = 0; k0 < K; k0 += HBK_T) {
        // A tile: 128 x 32, 16 elems per thread
#pragma unroll
        for (int it = 0; it < 16; it++) {
            int idx = tid + it * 256;
            int m = idx >> 5, kk = idx & 31;
            int gm = row0 + m, gk = k0 + kk;
            float v = (gm < M && gk < K) ? A[(long)gm * K + gk] : 0.f;
            __half hi = __float2half_rn(v);
            __half lo = __float2half_rn(v - __half2float(hi));
            sAh[m * HSA + kk] = hi;
            sAl[m * HSA + kk] = lo;
        }
        // B tile: 32 x 80, store transposed [n][k], 10 elems per thread
#pragma unroll
        for (int it = 0; it < 10; it++) {
            int idx = tid + it * 256;
            int kk = idx / 80, n = idx - kk * 80;
            int gk = k0 + kk, gn = col0 + n;
            float v = (gk < K && gn < Nc) ? W[(long)gk * Nc + gn] : 0.f;
            __half hi = __float2half_rn(v);
            __half lo = __float2half_rn(v - __half2float(hi));
            sBh[n * HSB + kk] = hi;
            sBl[n * HSB + kk] = lo;
        }
        __syncthreads();

#pragma unroll
        for (int ks = 0; ks < HBK_T; ks += 16) {
            uint32_t ah[2][4], al[2][4];
#pragma unroll
            for (int i = 0; i < 2; i++) {
                int r0 = wm * 32 + i * 16 + g;
                ah[i][0] = *(const uint32_t*)&sAh[r0 * HSA + ks + 2 * t];
                ah[i][1] = *(const uint32_t*)&sAh[(r0 + 8) * HSA + ks + 2 * t];
                ah[i][2] = *(const uint32_t*)&sAh[r0 * HSA + ks + 2 * t + 8];
                ah[i][3] = *(const uint32_t*)&sAh[(r0 + 8) * HSA + ks + 2 * t + 8];
                al[i][0] = *(const uint32_t*)&sAl[r0 * HSA + ks + 2 * t];
                al[i][1] = *(const uint32_t*)&sAl[(r0 + 8) * HSA + ks + 2 * t];
                al[i][2] = *(const uint32_t*)&sAl[r0 * HSA + ks + 2 * t + 8];
                al[i][3] = *(const uint32_t*)&sAl[(r0 + 8) * HSA + ks + 2 * t + 8];
            }
#pragma unroll
            for (int j = 0; j < 5; j++) {
                int c = wn * 40 + j * 8 + g;
                uint32_t bh0 = *(const uint32_t*)&sBh[c * HSB + ks + 2 * t];
                uint32_t bh1 = *(const uint32_t*)&sBh[c * HSB + ks + 2 * t + 8];
                uint32_t bl0 = *(const uint32_t*)&sBl[c * HSB + ks + 2 * t];
                uint32_t bl1 = *(const uint32_t*)&sBl[c * HSB + ks + 2 * t + 8];
#pragma unroll
                for (int i = 0; i < 2; i++) {
                    mma_f16(acc[i][j], ah[i][0], ah[i][1], ah[i][2], ah[i][3], bh0, bh1);
                    mma_f16(acc[i][j], ah[i][0], ah[i][1], ah[i][2], ah[i][3], bl0, bl1);
                    mma_f16(acc[i][j], al[i][0], al[i][1], al[i][2], al[i][3], bh0, bh1);
                }
            }
        }
        __syncthreads();
    }

    // epilogue: c0:(r, 2t) c1:(r, 2t+1) c2:(r+8, 2t) c3:(r+8, 2t+1)
#pragma unroll
    for (int i = 0; i < 2; i++) {
        int rbase = row0 + wm * 32 + i * 16 + g;
#pragma unroll
        for (int j = 0; j < 5; j++) {
            int cbase = col0 + wn * 40 + j * 8 + t * 2;
#pragma unroll
            for (int q = 0; q < 4; q++) {
                int gm = rbase + ((q >= 2) ? 8 : 0);
                int gn = cbase + (q & 1);
                if (gm < M && gn < Nc) {
                    float v = acc[i][j][q];
                    if (BIAS) v += bias[gn];
                    if (ACT == 1) v = fmaxf(v, 0.f);
                    if (OUTH) ((__half*)outv)[(long)gm * Nc + gn] = __float2half_rn(v);
                    else ((float*)outv)[(long)gm * Nc + gn] = v;
                }
            }
        }
    }
}

// ---------------- fused dense chain ----------------
__global__ void __launch_bounds__(256)
k_chain(const float* __restrict__ in, float* __restrict__ out,
        const float* __restrict__ w1, const float* __restrict__ b1,
        const float* __restrict__ w2, const float* __restrict__ b2,
        const float* __restrict__ w3, const float* __restrict__ b3,
        const float* __restrict__ w4, const float* __restrict__ b4) {
    __shared__ float sw1[200], sb1[10], sw2[30], sb2[3], sw3[30], sb3[10], sw4[200], sb4[20];
    int tid = threadIdx.x;
    for (int i = tid; i < 200; i += 256) sw1[i] = w1[i];
    for (int i = tid; i < 10; i += 256) sb1[i] = b1[i];
    for (int i = tid; i < 30; i += 256) sw2[i] = w2[i];
    for (int i = tid; i < 3; i += 256) sb2[i] = b2[i];
    for (int i = tid; i < 30; i += 256) sw3[i] = w3[i];
    for (int i = tid; i < 10; i += 256) sb3[i] = b3[i];
    for (int i = tid; i < 200; i += 256) sw4[i] = w4[i];
    for (int i = tid; i < 20; i += 256) sb4[i] = b4[i];
    __syncthreads();

    int n = blockIdx.x * blockDim.x + tid;
    if (n >= NN) return;
    float h0[20];
    const float4* ip = (const float4*)(in + (long)n * 20);
#pragma unroll
    for (int i = 0; i < 5; i++) {
        float4 v = __ldg(ip + i);
        h0[i * 4 + 0] = v.x; h0[i * 4 + 1] = v.y; h0[i * 4 + 2] = v.z; h0[i * 4 + 3] = v.w;
    }
    float h1[10];
#pragma unroll
    for (int j = 0; j < 10; j++) {
        float s = sb1[j];
#pragma unroll
        for (int i = 0; i < 20; i++) s = fmaf(h0[i], sw1[i * 10 + j], s);
        h1[j] = fmaxf(s, 0.f);
    }
    float z[3];
#pragma unroll
    for (int j = 0; j < 3; j++) {
        float s = sb2[j];
#pragma unroll
        for (int i = 0; i < 10; i++) s = fmaf(h1[i], sw2[i * 3 + j], s);
        z[j] = s;
    }
    float h2[10];
#pragma unroll
    for (int j = 0; j < 10; j++) {
        float s = sb3[j];
#pragma unroll
        for (int i = 0; i < 3; i++) s = fmaf(z[i], sw3[i * 10 + j], s);
        h2[j] = fmaxf(s, 0.f);
    }
    float* op = out + (long)n * 20;
#pragma unroll
    for (int j = 0; j < 20; j++) {
        float s = sb4[j];
#pragma unroll
        for (int i = 0; i < 10; i++) s = fmaf(h2[i], sw4[i * 20 + j], s);
        op[j] = fmaxf(s, 0.f);
    }
}

// ---------------- driver ----------------
template <int ACT, bool BIAS, bool OUTH>
static void gemm_h(const float* A, const float* W, const float* b, void* o, int K, int Nc) {
    dim3 g(cdiv(Nc, HBN_T), cdiv(NN, HBM_T));
    k_gemm_f16<ACT, BIAS, OUTH><<<g, 256>>>(A, W, b, o, NN, K, Nc);
}

extern "C" void kernel_launch(void* const* d_in, const int* in_sizes, int n_in,
                              void* d_out, int out_size) {
    const float* x = (const float*)d_in[0];
    const int* ei = (const int*)d_in[1];
    const int* src = ei;
    const int* dst = ei + NE;
    const float* W[12];
    const float* B[12];
    for (int i = 0; i < 12; i++) {
        W[i] = (const float*)d_in[2 + 2 * i];
        B[i] = (const float*)d_in[3 + 2 * i];
    }
    float* bufA; cudaGetSymbolAddress((void**)&bufA, g_bufA);
    float* bufB; cudaGetSymbolAddress((void**)&bufB, g_bufB);
    __half* bufH; cudaGetSymbolAddress((void**)&bufH, g_bufH);
    float* outp = (float*)d_out;

    const int NB = cdiv(NN, 1024);
    // CSR build (+ PROBE at launch index 3 so ncu captures the big GEMM's profile)
    k_init_cnt<<<cdiv(NN, 256), 256>>>();                       // 0
    k_count<<<cdiv(NE, 256), 256>>>(dst);                       // 1
    k_scan1<<<NB, 1024>>>();                                    // 2
    gemm_h<1, true, false>(bufA, W[10], B[10], bufB, 80, 160);  // 3: PROBE (scratch; bufB fully rewritten by eg1)
    k_scan2<<<1, 128>>>(NB);                                    // 4
    k_scan3<<<NB, 1024>>>();                                    // 5
    k_self<<<cdiv(NN, 256), 256>>>();                           // 6
    k_edges<<<cdiv(NE, 256), 256>>>(src, dst);                  // 7

    const int TPB = 256;
    int blocks16 = cdiv(cdiv(NN, 2) * 32, TPB);   // SUB=16
    int blocks8  = cdiv(cdiv(NN, 4) * 32, TPB);   // SUB=8
    int blocks4  = cdiv(cdiv(NN, 8) * 32, TPB);   // SUB=4 scalar C=3
    int blocksN  = cdiv(NN, TPB);                 // thread-per-node

    // encoder
    k_eg1<<<blocks4, TPB>>>(x, W[0], B[0], bufB);                        // fused agg+eg1
    gemm_h<0, false, true>(bufB, W[1], nullptr, bufH, 160, 80);          // eg2 matmul -> fp16
    k_aggvh<80, 16, 1, true><<<blocks16, TPB>>>(bufH, B[1], bufA);       // eg2 agg+b+relu
    gemm_h<0, false, true>(bufA, W[2], nullptr, bufH, 80, 40);           // eg3 matmul -> fp16
    k_aggvh<40, 8, 1, true><<<blocks8, TPB>>>(bufH, B[2], bufB);         // eg3 agg+b+relu
    k_dense<40, 20, 0, false, false><<<blocksN, TPB>>>(bufB, W[3], nullptr, bufA);  // eg4 matmul
    k_aggv<20, 8, 1, true><<<blocks8, TPB>>>(bufA, B[3], bufB);          // eg4 agg+b+relu
    // latent dense chain
    k_chain<<<blocksN, TPB>>>(bufB, bufA, W[4], B[4], W[5], B[5], W[6], B[6], W[7], B[7]);
    // decoder
    k_aggv<20, 8, 0, false><<<blocks8, TPB>>>(bufA, nullptr, bufB);      // dg1 agg
    k_dense<20, 40, 1, true, true><<<blocksN, TPB>>>(bufB, W[8], B[8], bufH);       // dg1 -> fp16
    k_aggvh<40, 8, 0, false><<<blocks8, TPB>>>(bufH, nullptr, bufA);     // dg2 agg
    gemm_h<1, true, true>(bufA, W[9], B[9], bufH, 40, 80);               // dg2 relu -> fp16
    k_aggvh<80, 16, 0, false><<<blocks16, TPB>>>(bufH, nullptr, bufB);   // dg3 agg
    gemm_h<1, true, false>(bufB, W[10], B[10], bufA, 80, 160);           // dg3 relu
    k_dense<160, 3, 0, false, false><<<blocksN, TPB>>>(bufA, W[11], nullptr, bufB); // dg4 matmul
    k_agg3<2, true><<<blocks4, TPB>>>(bufB, B[11], outp);                // dg4 agg+b+tanh
}

// round 8
// speedup vs baseline: 1.3911x; 1.3911x over previous
#include <cuda_runtime.h>
#include <cuda_fp16.h>
#include <cuda_bf16.h>
#include <cstdint>

#define NN 100000
#define NE 1600000
#define NTOT (NE + NN)

// ---------------- scratch (device globals: allocation-free) ----------------
__device__ float  g_bufA[NN * 160];
__device__ float  g_bufB[NN * 160];
__device__ __align__(16) __half g_bufH[NN * 80];
__device__ __align__(16) __half g_ah[NN * 160];   // GEMM A operand, hi halves
__device__ __align__(16) __half g_al[NN * 160];   // GEMM A operand, lo halves
__device__ __align__(16) __half g_wth[32000];     // transposed weights hi [n*K+k]
__device__ __align__(16) __half g_wtl[32000];     // transposed weights lo
__device__ int    g_cnt[NN];
__device__ float  g_dis[NN];
__device__ int    g_rowptr[NN + 1];
__device__ int    g_fill[NN];
__device__ int2   g_entries[NTOT];
__device__ int    g_bsums[128];

static inline int cdiv(int a, int b) { return (a + b - 1) / b; }

// weight scratch offsets (halves); all 16B aligned
#define WOFF_EG2 0        // W1: 160x80  -> 12800
#define WOFF_EG3 12800    // W2: 80x40   -> 3200
#define WOFF_DG2 16000    // W9: 40x80   -> 3200
#define WOFF_DG3 19200    // W10: 80x160 -> 12800

// ---------------- CSR build ----------------
__global__ void k_init_cnt() {
    int i = blockIdx.x * blockDim.x + threadIdx.x;
    if (i < NN) g_cnt[i] = 1;
}
__global__ void k_count(const int* __restrict__ dst) {
    int e = blockIdx.x * blockDim.x + threadIdx.x;
    if (e < NE) atomicAdd(&g_cnt[dst[e]], 1);
}
__global__ void k_scan1() {
    __shared__ int s[1024];
    int i = blockIdx.x * 1024 + threadIdx.x;
    int v = (i < NN) ? g_cnt[i] : 0;
    if (i < NN) g_dis[i] = rsqrtf((float)v);
    s[threadIdx.x] = v;
    __syncthreads();
    for (int d = 1; d < 1024; d <<= 1) {
        int t = (threadIdx.x >= d) ? s[threadIdx.x - d] : 0;
        __syncthreads();
        s[threadIdx.x] += t;
        __syncthreads();
    }
    if (i < NN) g_rowptr[i + 1] = s[threadIdx.x];
    if (threadIdx.x == 1023) g_bsums[blockIdx.x] = s[1023];
}
__global__ void k_scan2(int nb) {
    __shared__ int s[128];
    int v = (threadIdx.x < nb) ? g_bsums[threadIdx.x] : 0;
    s[threadIdx.x] = v;
    __syncthreads();
    for (int d = 1; d < 128; d <<= 1) {
        int t = (threadIdx.x >= d) ? s[threadIdx.x - d] : 0;
        __syncthreads();
        s[threadIdx.x] += t;
        __syncthreads();
    }
    if (threadIdx.x < nb) g_bsums[threadIdx.x] = s[threadIdx.x] - v;
}
__global__ void k_scan3() {
    int i = blockIdx.x * 1024 + threadIdx.x;
    if (i < NN) g_rowptr[i + 1] += g_bsums[blockIdx.x];
    if (i == 0) g_rowptr[0] = 0;
}
__global__ void k_self() {
    int i = blockIdx.x * blockDim.x + threadIdx.x;
    if (i < NN) {
        int p = g_rowptr[i];
        float d = g_dis[i];
        g_entries[p] = make_int2(i, __float_as_int(d * d));
        g_fill[i] = p + 1;
    }
}
__global__ void k_edges(const int* __restrict__ src, const int* __restrict__ dst) {
    int e = blockIdx.x * blockDim.x + threadIdx.x;
    if (e < NE) {
        int s = src[e], d = dst[e];
        int p = atomicAdd(&g_fill[d], 1);
        g_entries[p] = make_int2(s, __float_as_int(g_dis[s] * g_dis[d]));
    }
}

// ---------------- weight convert+transpose: W[k][n] f32 -> wt[n*K+k] hi/lo ----------------
__global__ void k_wconv(const float* __restrict__ W, int K, int Nc, int off) {
    int idx = blockIdx.x * blockDim.x + threadIdx.x;
    if (idx >= K * Nc) return;
    int k = idx / Nc, n = idx - k * Nc;
    float v = W[idx];
    __half h = __float2half_rn(v);
    __half l = __float2half_rn(v - __half2float(h));
    g_wth[off + n * K + k] = h;
    g_wtl[off + n * K + k] = l;
}

// ---------------- scalar aggregation (C=3) ----------------
template <int ACT, bool BIAS>
__global__ void k_agg3(const float* __restrict__ in, const float* __restrict__ bias,
                       float* __restrict__ out) {
    int gwarp = (blockIdx.x * blockDim.x + threadIdx.x) >> 5;
    int lane = threadIdx.x & 31;
    int node = gwarp * 8 + lane / 4;
    int cl = lane & 3;
    if (node >= NN) return;
    int p0 = g_rowptr[node], p1 = g_rowptr[node + 1];
    float acc = 0.f;
    bool act3 = (cl < 3);
    int p = p0;
    for (; p + 4 <= p1; p += 4) {
        int2 e0 = __ldg(&g_entries[p]);
        int2 e1 = __ldg(&g_entries[p + 1]);
        int2 e2 = __ldg(&g_entries[p + 2]);
        int2 e3 = __ldg(&g_entries[p + 3]);
        if (act3) {
            float v0 = __ldg(in + (long)e0.x * 3 + cl);
            float v1 = __ldg(in + (long)e1.x * 3 + cl);
            float v2 = __ldg(in + (long)e2.x * 3 + cl);
            float v3 = __ldg(in + (long)e3.x * 3 + cl);
            acc = fmaf(__int_as_float(e0.y), v0, acc);
            acc = fmaf(__int_as_float(e1.y), v1, acc);
            acc = fmaf(__int_as_float(e2.y), v2, acc);
            acc = fmaf(__int_as_float(e3.y), v3, acc);
        }
    }
    for (; p < p1; p++) {
        int2 e = __ldg(&g_entries[p]);
        if (act3) {
            float v = __ldg(in + (long)e.x * 3 + cl);
            acc = fmaf(__int_as_float(e.y), v, acc);
        }
    }
    if (act3) {
        float v = acc;
        if (BIAS) v += bias[cl];
        if (ACT == 1) v = fmaxf(v, 0.f);
        if (ACT == 2) v = tanhf(v);
        out[(long)node * 3 + cl] = v;
    }
}

// ---------------- fp32 vectorized aggregation ----------------
template <int C, int SUB, int ACT, bool BIAS>
__global__ void k_aggv(const float* __restrict__ in, const float* __restrict__ bias,
                       float* __restrict__ out) {
    constexpr int NV = C / 4;
    static_assert(NV <= SUB, "SUB too small");
    const int nodesPerWarp = 32 / SUB;
    int gwarp = (blockIdx.x * blockDim.x + threadIdx.x) >> 5;
    int lane = threadIdx.x & 31;
    int node = gwarp * nodesPerWarp + lane / SUB;
    int vl = lane % SUB;
    if (node >= NN) return;
    int p0 = g_rowptr[node], p1 = g_rowptr[node + 1];
    float4 acc = make_float4(0.f, 0.f, 0.f, 0.f);
    bool active = (vl < NV);
    int p = p0;
    for (; p + 4 <= p1; p += 4) {
        int2 e0 = __ldg(&g_entries[p]);
        int2 e1 = __ldg(&g_entries[p + 1]);
        int2 e2 = __ldg(&g_entries[p + 2]);
        int2 e3 = __ldg(&g_entries[p + 3]);
        if (active) {
            float4 v0 = __ldg((const float4*)(in + (long)e0.x * C) + vl);
            float4 v1 = __ldg((const float4*)(in + (long)e1.x * C) + vl);
            float4 v2 = __ldg((const float4*)(in + (long)e2.x * C) + vl);
            float4 v3 = __ldg((const float4*)(in + (long)e3.x * C) + vl);
            float w0 = __int_as_float(e0.y), w1 = __int_as_float(e1.y);
            float w2 = __int_as_float(e2.y), w3 = __int_as_float(e3.y);
            acc.x = fmaf(w0, v0.x, acc.x); acc.y = fmaf(w0, v0.y, acc.y);
            acc.z = fmaf(w0, v0.z, acc.z); acc.w = fmaf(w0, v0.w, acc.w);
            acc.x = fmaf(w1, v1.x, acc.x); acc.y = fmaf(w1, v1.y, acc.y);
            acc.z = fmaf(w1, v1.z, acc.z); acc.w = fmaf(w1, v1.w, acc.w);
            acc.x = fmaf(w2, v2.x, acc.x); acc.y = fmaf(w2, v2.y, acc.y);
            acc.z = fmaf(w2, v2.z, acc.z); acc.w = fmaf(w2, v2.w, acc.w);
            acc.x = fmaf(w3, v3.x, acc.x); acc.y = fmaf(w3, v3.y, acc.y);
            acc.z = fmaf(w3, v3.z, acc.z); acc.w = fmaf(w3, v3.w, acc.w);
        }
    }
    for (; p < p1; p++) {
        int2 e = __ldg(&g_entries[p]);
        if (active) {
            float w = __int_as_float(e.y);
            float4 v = __ldg((const float4*)(in + (long)e.x * C) + vl);
            acc.x = fmaf(w, v.x, acc.x); acc.y = fmaf(w, v.y, acc.y);
            acc.z = fmaf(w, v.z, acc.z); acc.w = fmaf(w, v.w, acc.w);
        }
    }
    if (active) {
        if (BIAS) {
            float4 bv = __ldg((const float4*)bias + vl);
            acc.x += bv.x; acc.y += bv.y; acc.z += bv.z; acc.w += bv.w;
        }
        if (ACT == 1) {
            acc.x = fmaxf(acc.x, 0.f); acc.y = fmaxf(acc.y, 0.f);
            acc.z = fmaxf(acc.z, 0.f); acc.w = fmaxf(acc.w, 0.f);
        }
        *((float4*)(out + (long)node * C) + vl) = acc;
    }
}

// ---------------- fp16-input aggregation; OM: 0=f32 out, 1=hi/lo half out ----------------
__device__ __forceinline__ void accum8h(float* acc, int4 h, float w) {
    const __half2* hp = (const __half2*)&h;
#pragma unroll
    for (int i = 0; i < 4; i++) {
        float2 f = __half22float2(hp[i]);
        acc[2 * i]     = fmaf(w, f.x, acc[2 * i]);
        acc[2 * i + 1] = fmaf(w, f.y, acc[2 * i + 1]);
    }
}

template <int C, int SUB, int ACT, bool BIAS, int OM>
__global__ void k_aggvh(const __half* __restrict__ in, const float* __restrict__ bias,
                        float* __restrict__ out, __half* __restrict__ oh,
                        __half* __restrict__ ol) {
    constexpr int NV = C / 8;
    static_assert(NV <= SUB, "SUB too small");
    const int nodesPerWarp = 32 / SUB;
    int gwarp = (blockIdx.x * blockDim.x + threadIdx.x) >> 5;
    int lane = threadIdx.x & 31;
    int node = gwarp * nodesPerWarp + lane / SUB;
    int vl = lane % SUB;
    if (node >= NN) return;
    int p0 = g_rowptr[node], p1 = g_rowptr[node + 1];
    float acc[8] = {};
    bool active = (vl < NV);
    int p = p0;
    for (; p + 4 <= p1; p += 4) {
        int2 e0 = __ldg(&g_entries[p]);
        int2 e1 = __ldg(&g_entries[p + 1]);
        int2 e2 = __ldg(&g_entries[p + 2]);
        int2 e3 = __ldg(&g_entries[p + 3]);
        if (active) {
            int4 h0 = __ldg((const int4*)(in + (long)e0.x * C) + vl);
            int4 h1 = __ldg((const int4*)(in + (long)e1.x * C) + vl);
            int4 h2 = __ldg((const int4*)(in + (long)e2.x * C) + vl);
            int4 h3 = __ldg((const int4*)(in + (long)e3.x * C) + vl);
            accum8h(acc, h0, __int_as_float(e0.y));
            accum8h(acc, h1, __int_as_float(e1.y));
            accum8h(acc, h2, __int_as_float(e2.y));
            accum8h(acc, h3, __int_as_float(e3.y));
        }
    }
    for (; p < p1; p++) {
        int2 e = __ldg(&g_entries[p]);
        if (active) {
            int4 h = __ldg((const int4*)(in + (long)e.x * C) + vl);
            accum8h(acc, h, __int_as_float(e.y));
        }
    }
    if (active) {
        if (BIAS) {
            const float4* bp = (const float4*)bias + vl * 2;
            float4 b0 = __ldg(bp), b1 = __ldg(bp + 1);
            acc[0] += b0.x; acc[1] += b0.y; acc[2] += b0.z; acc[3] += b0.w;
            acc[4] += b1.x; acc[5] += b1.y; acc[6] += b1.z; acc[7] += b1.w;
        }
        if (ACT == 1) {
#pragma unroll
            for (int i = 0; i < 8; i++) acc[i] = fmaxf(acc[i], 0.f);
        }
        if (OM == 0) {
            float4* op = (float4*)(out + (long)node * C) + vl * 2;
            op[0] = make_float4(acc[0], acc[1], acc[2], acc[3]);
            op[1] = make_float4(acc[4], acc[5], acc[6], acc[7]);
        } else {
            __half hh[8], ll[8];
#pragma unroll
            for (int i = 0; i < 8; i++) {
                hh[i] = __float2half_rn(acc[i]);
                ll[i] = __float2half_rn(acc[i] - __half2float(hh[i]));
            }
            *((int4*)(oh + (long)node * C) + vl) = *(const int4*)hh;
            *((int4*)(ol + (long)node * C) + vl) = *(const int4*)ll;
        }
    }
}

// ---------------- fused eg1 -> hi/lo halves for eg2 GEMM ----------------
__global__ void __launch_bounds__(256)
k_eg1(const float* __restrict__ x, const float* __restrict__ W,
      const float* __restrict__ Bb, __half* __restrict__ oh, __half* __restrict__ ol) {
    __shared__ float sW[480];
    __shared__ float sB[160];
    for (int i = threadIdx.x; i < 480; i += 256) sW[i] = W[i];
    for (int i = threadIdx.x; i < 160; i += 256) sB[i] = Bb[i];
    __syncthreads();
    int gwarp = (blockIdx.x * blockDim.x + threadIdx.x) >> 5;
    int lane = threadIdx.x & 31;
    int nodeBase = gwarp * 8;
    int node = nodeBase + lane / 4;
    int cl = lane & 3;
    float acc = 0.f;
    if (node < NN) {
        int p0 = g_rowptr[node], p1 = g_rowptr[node + 1];
        bool act3 = (cl < 3);
        int p = p0;
        for (; p + 4 <= p1; p += 4) {
            int2 e0 = __ldg(&g_entries[p]);
            int2 e1 = __ldg(&g_entries[p + 1]);
            int2 e2 = __ldg(&g_entries[p + 2]);
            int2 e3 = __ldg(&g_entries[p + 3]);
            if (act3) {
                float v0 = __ldg(x + (long)e0.x * 3 + cl);
                float v1 = __ldg(x + (long)e1.x * 3 + cl);
                float v2 = __ldg(x + (long)e2.x * 3 + cl);
                float v3 = __ldg(x + (long)e3.x * 3 + cl);
                acc = fmaf(__int_as_float(e0.y), v0, acc);
                acc = fmaf(__int_as_float(e1.y), v1, acc);
                acc = fmaf(__int_as_float(e2.y), v2, acc);
                acc = fmaf(__int_as_float(e3.y), v3, acc);
            }
        }
        for (; p < p1; p++) {
            int2 e = __ldg(&g_entries[p]);
            if (act3) {
                float v = __ldg(x + (long)e.x * 3 + cl);
                acc = fmaf(__int_as_float(e.y), v, acc);
            }
        }
    }
#pragma unroll
    for (int j = 0; j < 8; j++) {
        int n2 = nodeBase + j;
        float a0 = __shfl_sync(0xffffffffu, acc, j * 4 + 0);
        float a1 = __shfl_sync(0xffffffffu, acc, j * 4 + 1);
        float a2 = __shfl_sync(0xffffffffu, acc, j * 4 + 2);
        if (n2 >= NN) break;
#pragma unroll
        for (int c0 = 0; c0 < 160; c0 += 32) {
            int c = c0 + lane;
            float v = sB[c];
            v = fmaf(a0, sW[c], v);
            v = fmaf(a1, sW[160 + c], v);
            v = fmaf(a2, sW[320 + c], v);
            v = fmaxf(v, 0.f);
            __half h = __float2half_rn(v);
            oh[(long)n2 * 160 + c] = h;
            ol[(long)n2 * 160 + c] = __float2half_rn(v - __half2float(h));
        }
    }
}

// ---------------- thread-per-node dense ----------------
template <int K, int NC, int ACT, bool BIAS, bool OUTH>
__global__ void __launch_bounds__(256)
k_dense(const float* __restrict__ in, const float* __restrict__ W,
        const float* __restrict__ bias, void* __restrict__ outv) {
    __shared__ float sW[K * NC];
    __shared__ float sB[NC];
    for (int i = threadIdx.x; i < K * NC; i += 256) sW[i] = W[i];
    if (BIAS) for (int i = threadIdx.x; i < NC; i += 256) sB[i] = bias[i];
    __syncthreads();
    int n = blockIdx.x * blockDim.x + threadIdx.x;
    if (n >= NN) return;
    float acc[NC];
#pragma unroll
    for (int c = 0; c < NC; c++) acc[c] = BIAS ? sB[c] : 0.f;
    const float4* ip = (const float4*)(in + (long)n * K);
#pragma unroll
    for (int k4 = 0; k4 < K / 4; k4++) {
        float4 v = __ldg(ip + k4);
#pragma unroll
        for (int c = 0; c < NC; c++) {
            acc[c] = fmaf(v.x, sW[(k4 * 4 + 0) * NC + c], acc[c]);
            acc[c] = fmaf(v.y, sW[(k4 * 4 + 1) * NC + c], acc[c]);
            acc[c] = fmaf(v.z, sW[(k4 * 4 + 2) * NC + c], acc[c]);
            acc[c] = fmaf(v.w, sW[(k4 * 4 + 3) * NC + c], acc[c]);
        }
    }
#pragma unroll
    for (int c = 0; c < NC; c++) {
        float v = acc[c];
        if (ACT == 1) v = fmaxf(v, 0.f);
        if (OUTH) ((__half*)outv)[(long)n * NC + c] = __float2half_rn(v);
        else ((float*)outv)[(long)n * NC + c] = v;
    }
}

// ---------------- fp16-split tensor GEMM, pre-split operands ----------------
__device__ __forceinline__ void mma_f16(float* c, uint32_t a0, uint32_t a1,
                                        uint32_t a2, uint32_t a3,
                                        uint32_t b0, uint32_t b1) {
    asm volatile(
        "mma.sync.aligned.m16n8k16.row.col.f32.f16.f16.f32 "
        "{%0,%1,%2,%3}, {%4,%5,%6,%7}, {%8,%9}, {%0,%1,%2,%3};\n"
        : "+f"(c[0]), "+f"(c[1]), "+f"(c[2]), "+f"(c[3])
        : "r"(a0), "r"(a1), "r"(a2), "r"(a3), "r"(b0), "r"(b1));
}

#define HBM_T 128
#define HBN_T 80
#define HBK_T 32
#define HSA 40
#define HSB 40

template <int ACT, bool BIAS, int OUTM>   // OUTM: 0 f32, 1 half
__global__ void __launch_bounds__(256, 2)
k_gemm_hl(const __half* __restrict__ Ah, const __half* __restrict__ Al,
          const __half* __restrict__ Bth, const __half* __restrict__ Btl,
          const float* __restrict__ bias, void* __restrict__ outv,
          int M, int K, int Nc) {
    __shared__ __half sAh[HBM_T * HSA];
    __shared__ __half sAl[HBM_T * HSA];
    __shared__ __half sBh[HBN_T * HSB];
    __shared__ __half sBl[HBN_T * HSB];

    int tid = threadIdx.x;
    int wid = tid >> 5;
    int lane = tid & 31;
    int g = lane >> 2;
    int t = lane & 3;
    int wm = wid & 3;
    int wn = wid >> 2;
    int row0 = blockIdx.y * HBM_T;
    int col0 = blockIdx.x * HBN_T;

    float acc[2][5][4];
#pragma unroll
    for (int i = 0; i < 2; i++)
#pragma unroll
        for (int j = 0; j < 5; j++)
#pragma unroll
            for (int q = 0; q < 4; q++) acc[i][j][q] = 0.f;

    const int4 z4 = make_int4(0, 0, 0, 0);
    for (int k0 = 0; k0 < K; k0 += HBK_T) {
        // A tile copy: 128 rows x 32 halves = 512 int4 per buffer, 2 per thread.
        // Guard each 8-half group against K overrun (K % 8 == 0 always).
#pragma unroll
        for (int it = 0; it < 2; it++) {
            int idx = tid + it * 256;
            int m = idx >> 2, kq = idx & 3;
            int gm = row0 + m;
            int gk = k0 + kq * 8;
            bool ok = (gm < M) && (gk < K);
            long goff = (long)gm * K + gk;
            int soff = m * HSA + kq * 8;
            *(int4*)&sAh[soff] = ok ? *(const int4*)&Ah[goff] : z4;
            *(int4*)&sAl[soff] = ok ? *(const int4*)&Al[goff] : z4;
        }
        // B tile copy: 80 rows x 32 halves = 320 int4 per buffer
#pragma unroll
        for (int it = 0; it < 2; it++) {
            int idx = tid + it * 256;
            if (idx < 320) {
                int n = idx >> 2, kq = idx & 3;
                int gk = k0 + kq * 8;
                bool ok = (gk < K);
                long goff = (long)(col0 + n) * K + gk;
                int soff = n * HSB + kq * 8;
                *(int4*)&sBh[soff] = ok ? *(const int4*)&Bth[goff] : z4;
                *(int4*)&sBl[soff] = ok ? *(const int4*)&Btl[goff] : z4;
            }
        }
        __syncthreads();

#pragma unroll
        for (int ks = 0; ks < HBK_T; ks += 16) {
            uint32_t ah[2][4], al[2][4];
#pragma unroll
            for (int i = 0; i < 2; i++) {
                int r0 = wm * 32 + i * 16 + g;
                ah[i][0] = *(const uint32_t*)&sAh[r0 * HSA + ks + 2 * t];
                ah[i][1] = *(const uint32_t*)&sAh[(r0 + 8) * HSA + ks + 2 * t];
                ah[i][2] = *(const uint32_t*)&sAh[r0 * HSA + ks + 2 * t + 8];
                ah[i][3] = *(const uint32_t*)&sAh[(r0 + 8) * HSA + ks + 2 * t + 8];
                al[i][0] = *(const uint32_t*)&sAl[r0 * HSA + ks + 2 * t];
                al[i][1] = *(const uint32_t*)&sAl[(r0 + 8) * HSA + ks + 2 * t];
                al[i][2] = *(const uint32_t*)&sAl[r0 * HSA + ks + 2 * t + 8];
                al[i][3] = *(const uint32_t*)&sAl[(r0 + 8) * HSA + ks + 2 * t + 8];
            }
#pragma unroll
            for (int j = 0; j < 5; j++) {
                int c = wn * 40 + j * 8 + g;
                uint32_t bh0 = *(const uint32_t*)&sBh[c * HSB + ks + 2 * t];
                uint32_t bh1 = *(const uint32_t*)&sBh[c * HSB + ks + 2 * t + 8];
                uint32_t bl0 = *(const uint32_t*)&sBl[c * HSB + ks + 2 * t];
                uint32_t bl1 = *(const uint32_t*)&sBl[c * HSB + ks + 2 * t + 8];
#pragma unroll
                for (int i = 0; i < 2; i++) {
                    mma_f16(acc[i][j], ah[i][0], ah[i][1], ah[i][2], ah[i][3], bh0, bh1);
                    mma_f16(acc[i][j], ah[i][0], ah[i][1], ah[i][2], ah[i][3], bl0, bl1);
                    mma_f16(acc[i][j], al[i][0], al[i][1], al[i][2], al[i][3], bh0, bh1);
                }
            }
        }
        __syncthreads();
    }

#pragma unroll
    for (int i = 0; i < 2; i++) {
        int rbase = row0 + wm * 32 + i * 16 + g;
#pragma unroll
        for (int j = 0; j < 5; j++) {
            int cbase = col0 + wn * 40 + j * 8 + t * 2;
#pragma unroll
            for (int q = 0; q < 4; q++) {
                int gm = rbase + ((q >= 2) ? 8 : 0);
                int gn = cbase + (q & 1);
                if (gm < M && gn < Nc) {
                    float v = acc[i][j][q];
                    if (BIAS) v += bias[gn];
                    if (ACT == 1) v = fmaxf(v, 0.f);
                    if (OUTM == 1) ((__half*)outv)[(long)gm * Nc + gn] = __float2half_rn(v);
                    else ((float*)outv)[(long)gm * Nc + gn] = v;
                }
            }
        }
    }
}

// ---------------- fused dense chain ----------------
__global__ void __launch_bounds__(256)
k_chain(const float* __restrict__ in, float* __restrict__ out,
        const float* __restrict__ w1, const float* __restrict__ b1,
        const float* __restrict__ w2, const float* __restrict__ b2,
        const float* __restrict__ w3, const float* __restrict__ b3,
        const float* __restrict__ w4, const float* __restrict__ b4) {
    __shared__ float sw1[200], sb1[10], sw2[30], sb2[3], sw3[30], sb3[10], sw4[200], sb4[20];
    int tid = threadIdx.x;
    for (int i = tid; i < 200; i += 256) sw1[i] = w1[i];
    for (int i = tid; i < 10; i += 256) sb1[i] = b1[i];
    for (int i = tid; i < 30; i += 256) sw2[i] = w2[i];
    for (int i = tid; i < 3; i += 256) sb2[i] = b2[i];
    for (int i = tid; i < 30; i += 256) sw3[i] = w3[i];
    for (int i = tid; i < 10; i += 256) sb3[i] = b3[i];
    for (int i = tid; i < 200; i += 256) sw4[i] = w4[i];
    for (int i = tid; i < 20; i += 256) sb4[i] = b4[i];
    __syncthreads();

    int n = blockIdx.x * blockDim.x + tid;
    if (n >= NN) return;
    float h0[20];
    const float4* ip = (const float4*)(in + (long)n * 20);
#pragma unroll
    for (int i = 0; i < 5; i++) {
        float4 v = __ldg(ip + i);
        h0[i * 4 + 0] = v.x; h0[i * 4 + 1] = v.y; h0[i * 4 + 2] = v.z; h0[i * 4 + 3] = v.w;
    }
    float h1[10];
#pragma unroll
    for (int j = 0; j < 10; j++) {
        float s = sb1[j];
#pragma unroll
        for (int i = 0; i < 20; i++) s = fmaf(h0[i], sw1[i * 10 + j], s);
        h1[j] = fmaxf(s, 0.f);
    }
    float z[3];
#pragma unroll
    for (int j = 0; j < 3; j++) {
        float s = sb2[j];
#pragma unroll
        for (int i = 0; i < 10; i++) s = fmaf(h1[i], sw2[i * 3 + j], s);
        z[j] = s;
    }
    float h2[10];
#pragma unroll
    for (int j = 0; j < 10; j++) {
        float s = sb3[j];
#pragma unroll
        for (int i = 0; i < 3; i++) s = fmaf(z[i], sw3[i * 10 + j], s);
        h2[j] = fmaxf(s, 0.f);
    }
    float* op = out + (long)n * 20;
#pragma unroll
    for (int j = 0; j < 20; j++) {
        float s = sb4[j];
#pragma unroll
        for (int i = 0; i < 10; i++) s = fmaf(h2[i], sw4[i * 20 + j], s);
        op[j] = fmaxf(s, 0.f);
    }
}

// ---------------- driver ----------------
template <int ACT, bool BIAS, int OUTM>
static void gemm_hl(const __half* Ah, const __half* Al, const __half* Bth,
                    const __half* Btl, const float* b, void* o, int K, int Nc) {
    dim3 g(cdiv(Nc, HBN_T), cdiv(NN, HBM_T));
    k_gemm_hl<ACT, BIAS, OUTM><<<g, 256>>>(Ah, Al, Bth, Btl, b, o, NN, K, Nc);
}

extern "C" void kernel_launch(void* const* d_in, const int* in_sizes, int n_in,
                              void* d_out, int out_size) {
    const float* x = (const float*)d_in[0];
    const int* ei = (const int*)d_in[1];
    const int* src = ei;
    const int* dst = ei + NE;
    const float* W[12];
    const float* B[12];
    for (int i = 0; i < 12; i++) {
        W[i] = (const float*)d_in[2 + 2 * i];
        B[i] = (const float*)d_in[3 + 2 * i];
    }
    float* bufA; cudaGetSymbolAddress((void**)&bufA, g_bufA);
    float* bufB; cudaGetSymbolAddress((void**)&bufB, g_bufB);
    __half* bufH; cudaGetSymbolAddress((void**)&bufH, g_bufH);
    __half* ah; cudaGetSymbolAddress((void**)&ah, g_ah);
    __half* al; cudaGetSymbolAddress((void**)&al, g_al);
    __half* wth; cudaGetSymbolAddress((void**)&wth, g_wth);
    __half* wtl; cudaGetSymbolAddress((void**)&wtl, g_wtl);
    float* outp = (float*)d_out;

    const int NB = cdiv(NN, 1024);
    // weight conversion (tiny)
    k_wconv<<<cdiv(160 * 80, 256), 256>>>(W[1], 160, 80, WOFF_EG2);
    k_wconv<<<cdiv(80 * 40, 256), 256>>>(W[2], 80, 40, WOFF_EG3);
    k_wconv<<<cdiv(40 * 80, 256), 256>>>(W[9], 40, 80, WOFF_DG2);
    k_wconv<<<cdiv(80 * 160, 256), 256>>>(W[10], 80, 160, WOFF_DG3);
    // CSR build
    k_init_cnt<<<cdiv(NN, 256), 256>>>();
    k_count<<<cdiv(NE, 256), 256>>>(dst);
    k_scan1<<<NB, 1024>>>();
    k_scan2<<<1, 128>>>(NB);
    k_scan3<<<NB, 1024>>>();
    k_self<<<cdiv(NN, 256), 256>>>();
    k_edges<<<cdiv(NE, 256), 256>>>(src, dst);

    const int TPB = 256;
    int blocks16 = cdiv(cdiv(NN, 2) * 32, TPB);
    int blocks8  = cdiv(cdiv(NN, 4) * 32, TPB);
    int blocks4  = cdiv(cdiv(NN, 8) * 32, TPB);
    int blocksN  = cdiv(NN, TPB);

    // encoder
    k_eg1<<<blocks4, TPB>>>(x, W[0], B[0], ah, al);                        // fused agg+eg1 -> hi/lo
    gemm_hl<0, false, 1>(ah, al, wth + WOFF_EG2, wtl + WOFF_EG2, nullptr, bufH, 160, 80);  // eg2
    k_aggvh<80, 16, 1, true, 1><<<blocks16, TPB>>>(bufH, B[1], nullptr, ah, al);           // eg2 agg -> hi/lo
    gemm_hl<0, false, 1>(ah, al, wth + WOFF_EG3, wtl + WOFF_EG3, nullptr, bufH, 80, 40);   // eg3
    k_aggvh<40, 8, 1, true, 0><<<blocks8, TPB>>>(bufH, B[2], bufB, nullptr, nullptr);      // eg3 agg
    k_dense<40, 20, 0, false, false><<<blocksN, TPB>>>(bufB, W[3], nullptr, bufA);         // eg4 matmul
    k_aggv<20, 8, 1, true><<<blocks8, TPB>>>(bufA, B[3], bufB);                            // eg4 agg
    // latent dense chain
    k_chain<<<blocksN, TPB>>>(bufB, bufA, W[4], B[4], W[5], B[5], W[6], B[6], W[7], B[7]);
    // decoder
    k_aggv<20, 8, 0, false><<<blocks8, TPB>>>(bufA, nullptr, bufB);                        // dg1 agg
    k_dense<20, 40, 1, true, true><<<blocksN, TPB>>>(bufB, W[8], B[8], bufH);              // dg1 -> fp16
    k_aggvh<40, 8, 0, false, 1><<<blocks8, TPB>>>(bufH, nullptr, nullptr, ah, al);         // dg2 agg -> hi/lo
    gemm_hl<1, true, 1>(ah, al, wth + WOFF_DG2, wtl + WOFF_DG2, B[9], bufH, 40, 80);       // dg2
    k_aggvh<80, 16, 0, false, 1><<<blocks16, TPB>>>(bufH, nullptr, nullptr, ah, al);       // dg3 agg -> hi/lo
    gemm_hl<1, true, 0>(ah, al, wth + WOFF_DG3, wtl + WOFF_DG3, B[10], bufA, 80, 160);     // dg3
    k_dense<160, 3, 0, false, false><<<blocksN, TPB>>>(bufA, W[11], nullptr, bufB);        // dg4 matmul
    k_agg3<2, true><<<blocks4, TPB>>>(bufB, B[11], outp);                                  // dg4 agg+tanh
}

// round 9
// speedup vs baseline: 1.5826x; 1.1376x over previous
#include <cuda_runtime.h>
#include <cuda_fp16.h>
#include <cuda_bf16.h>
#include <cstdint>

#define NN 100000
#define NE 1600000
#define NTOT (NE + NN)

// ---------------- scratch (device globals: allocation-free) ----------------
__device__ float  g_bufA[NN * 160];
__device__ float  g_bufB[NN * 160];
__device__ __align__(16) __half g_bufH[NN * 80];
__device__ __align__(16) __half g_ah[NN * 160];   // GEMM A operand (fp16)
__device__ __align__(16) __half g_wth[32000];     // transposed weights [n*K+k] fp16
__device__ int    g_cnt[NN];
__device__ float  g_dis[NN];
__device__ int    g_rowptr[NN + 1];
__device__ int    g_fill[NN];
__device__ int2   g_entries[NTOT];
__device__ int    g_bsums[128];

static inline int cdiv(int a, int b) { return (a + b - 1) / b; }

// weight scratch offsets (halves); all 16B aligned
#define WOFF_EG2 0        // W1: 160x80  -> 12800
#define WOFF_EG3 12800    // W2: 80x40   -> 3200
#define WOFF_DG2 16000    // W9: 40x80   -> 3200
#define WOFF_DG3 19200    // W10: 80x160 -> 12800

// ---------------- CSR build ----------------
__global__ void k_init_cnt() {
    int i = blockIdx.x * blockDim.x + threadIdx.x;
    if (i < NN) g_cnt[i] = 1;
}
__global__ void k_count(const int* __restrict__ dst) {
    int e = blockIdx.x * blockDim.x + threadIdx.x;
    if (e < NE) atomicAdd(&g_cnt[dst[e]], 1);
}
__global__ void k_scan1() {
    __shared__ int s[1024];
    int i = blockIdx.x * 1024 + threadIdx.x;
    int v = (i < NN) ? g_cnt[i] : 0;
    if (i < NN) g_dis[i] = rsqrtf((float)v);
    s[threadIdx.x] = v;
    __syncthreads();
    for (int d = 1; d < 1024; d <<= 1) {
        int t = (threadIdx.x >= d) ? s[threadIdx.x - d] : 0;
        __syncthreads();
        s[threadIdx.x] += t;
        __syncthreads();
    }
    if (i < NN) g_rowptr[i + 1] = s[threadIdx.x];
    if (threadIdx.x == 1023) g_bsums[blockIdx.x] = s[1023];
}
__global__ void k_scan2(int nb) {
    __shared__ int s[128];
    int v = (threadIdx.x < nb) ? g_bsums[threadIdx.x] : 0;
    s[threadIdx.x] = v;
    __syncthreads();
    for (int d = 1; d < 128; d <<= 1) {
        int t = (threadIdx.x >= d) ? s[threadIdx.x - d] : 0;
        __syncthreads();
        s[threadIdx.x] += t;
        __syncthreads();
    }
    if (threadIdx.x < nb) g_bsums[threadIdx.x] = s[threadIdx.x] - v;
}
__global__ void k_scan3() {
    int i = blockIdx.x * 1024 + threadIdx.x;
    if (i < NN) g_rowptr[i + 1] += g_bsums[blockIdx.x];
    if (i == 0) g_rowptr[0] = 0;
}
__global__ void k_self() {
    int i = blockIdx.x * blockDim.x + threadIdx.x;
    if (i < NN) {
        int p = g_rowptr[i];
        float d = g_dis[i];
        g_entries[p] = make_int2(i, __float_as_int(d * d));
        g_fill[i] = p + 1;
    }
}
__global__ void k_edges(const int* __restrict__ src, const int* __restrict__ dst) {
    int e = blockIdx.x * blockDim.x + threadIdx.x;
    if (e < NE) {
        int s = src[e], d = dst[e];
        int p = atomicAdd(&g_fill[d], 1);
        g_entries[p] = make_int2(s, __float_as_int(g_dis[s] * g_dis[d]));
    }
}

// ---------------- all-weights convert+transpose (single launch) ----------------
__global__ void k_wconv_all(const float* __restrict__ W1, const float* __restrict__ W2,
                            const float* __restrict__ W9, const float* __restrict__ W10) {
    int idx = blockIdx.x * blockDim.x + threadIdx.x;
    if (idx >= 32000) return;
    const float* W; int K, Nc, off, li;
    if (idx < 12800)      { W = W1;  K = 160; Nc = 80;  off = WOFF_EG2; li = idx; }
    else if (idx < 16000) { W = W2;  K = 80;  Nc = 40;  off = WOFF_EG3; li = idx - 12800; }
    else if (idx < 19200) { W = W9;  K = 40;  Nc = 80;  off = WOFF_DG2; li = idx - 16000; }
    else                  { W = W10; K = 80;  Nc = 160; off = WOFF_DG3; li = idx - 19200; }
    int k = li / Nc, n = li - k * Nc;
    g_wth[off + n * K + k] = __float2half_rn(W[li]);
}

// ---------------- scalar aggregation (C=3) ----------------
template <int ACT, bool BIAS>
__global__ void k_agg3(const float* __restrict__ in, const float* __restrict__ bias,
                       float* __restrict__ out) {
    int gwarp = (blockIdx.x * blockDim.x + threadIdx.x) >> 5;
    int lane = threadIdx.x & 31;
    int node = gwarp * 8 + lane / 4;
    int cl = lane & 3;
    if (node >= NN) return;
    int p0 = g_rowptr[node], p1 = g_rowptr[node + 1];
    float acc = 0.f;
    bool act3 = (cl < 3);
    int p = p0;
    for (; p + 4 <= p1; p += 4) {
        int2 e0 = __ldg(&g_entries[p]);
        int2 e1 = __ldg(&g_entries[p + 1]);
        int2 e2 = __ldg(&g_entries[p + 2]);
        int2 e3 = __ldg(&g_entries[p + 3]);
        if (act3) {
            float v0 = __ldg(in + (long)e0.x * 3 + cl);
            float v1 = __ldg(in + (long)e1.x * 3 + cl);
            float v2 = __ldg(in + (long)e2.x * 3 + cl);
            float v3 = __ldg(in + (long)e3.x * 3 + cl);
            acc = fmaf(__int_as_float(e0.y), v0, acc);
            acc = fmaf(__int_as_float(e1.y), v1, acc);
            acc = fmaf(__int_as_float(e2.y), v2, acc);
            acc = fmaf(__int_as_float(e3.y), v3, acc);
        }
    }
    for (; p < p1; p++) {
        int2 e = __ldg(&g_entries[p]);
        if (act3) {
            float v = __ldg(in + (long)e.x * 3 + cl);
            acc = fmaf(__int_as_float(e.y), v, acc);
        }
    }
    if (act3) {
        float v = acc;
        if (BIAS) v += bias[cl];
        if (ACT == 1) v = fmaxf(v, 0.f);
        if (ACT == 2) v = tanhf(v);
        out[(long)node * 3 + cl] = v;
    }
}

// ---------------- fp32 vectorized aggregation ----------------
template <int C, int SUB, int ACT, bool BIAS>
__global__ void k_aggv(const float* __restrict__ in, const float* __restrict__ bias,
                       float* __restrict__ out) {
    constexpr int NV = C / 4;
    static_assert(NV <= SUB, "SUB too small");
    const int nodesPerWarp = 32 / SUB;
    int gwarp = (blockIdx.x * blockDim.x + threadIdx.x) >> 5;
    int lane = threadIdx.x & 31;
    int node = gwarp * nodesPerWarp + lane / SUB;
    int vl = lane % SUB;
    if (node >= NN) return;
    int p0 = g_rowptr[node], p1 = g_rowptr[node + 1];
    float4 acc = make_float4(0.f, 0.f, 0.f, 0.f);
    bool active = (vl < NV);
    int p = p0;
    for (; p + 4 <= p1; p += 4) {
        int2 e0 = __ldg(&g_entries[p]);
        int2 e1 = __ldg(&g_entries[p + 1]);
        int2 e2 = __ldg(&g_entries[p + 2]);
        int2 e3 = __ldg(&g_entries[p + 3]);
        if (active) {
            float4 v0 = __ldg((const float4*)(in + (long)e0.x * C) + vl);
            float4 v1 = __ldg((const float4*)(in + (long)e1.x * C) + vl);
            float4 v2 = __ldg((const float4*)(in + (long)e2.x * C) + vl);
            float4 v3 = __ldg((const float4*)(in + (long)e3.x * C) + vl);
            float w0 = __int_as_float(e0.y), w1 = __int_as_float(e1.y);
            float w2 = __int_as_float(e2.y), w3 = __int_as_float(e3.y);
            acc.x = fmaf(w0, v0.x, acc.x); acc.y = fmaf(w0, v0.y, acc.y);
            acc.z = fmaf(w0, v0.z, acc.z); acc.w = fmaf(w0, v0.w, acc.w);
            acc.x = fmaf(w1, v1.x, acc.x); acc.y = fmaf(w1, v1.y, acc.y);
            acc.z = fmaf(w1, v1.z, acc.z); acc.w = fmaf(w1, v1.w, acc.w);
            acc.x = fmaf(w2, v2.x, acc.x); acc.y = fmaf(w2, v2.y, acc.y);
            acc.z = fmaf(w2, v2.z, acc.z); acc.w = fmaf(w2, v2.w, acc.w);
            acc.x = fmaf(w3, v3.x, acc.x); acc.y = fmaf(w3, v3.y, acc.y);
            acc.z = fmaf(w3, v3.z, acc.z); acc.w = fmaf(w3, v3.w, acc.w);
        }
    }
    for (; p < p1; p++) {
        int2 e = __ldg(&g_entries[p]);
        if (active) {
            float w = __int_as_float(e.y);
            float4 v = __ldg((const float4*)(in + (long)e.x * C) + vl);
            acc.x = fmaf(w, v.x, acc.x); acc.y = fmaf(w, v.y, acc.y);
            acc.z = fmaf(w, v.z, acc.z); acc.w = fmaf(w, v.w, acc.w);
        }
    }
    if (active) {
        if (BIAS) {
            float4 bv = __ldg((const float4*)bias + vl);
            acc.x += bv.x; acc.y += bv.y; acc.z += bv.z; acc.w += bv.w;
        }
        if (ACT == 1) {
            acc.x = fmaxf(acc.x, 0.f); acc.y = fmaxf(acc.y, 0.f);
            acc.z = fmaxf(acc.z, 0.f); acc.w = fmaxf(acc.w, 0.f);
        }
        *((float4*)(out + (long)node * C) + vl) = acc;
    }
}

// ---------------- fp16-input aggregation; OM: 0=f32 out, 1=fp16 out ----------------
__device__ __forceinline__ void accum8h(float* acc, int4 h, float w) {
    const __half2* hp = (const __half2*)&h;
#pragma unroll
    for (int i = 0; i < 4; i++) {
        float2 f = __half22float2(hp[i]);
        acc[2 * i]     = fmaf(w, f.x, acc[2 * i]);
        acc[2 * i + 1] = fmaf(w, f.y, acc[2 * i + 1]);
    }
}

template <int C, int SUB, int ACT, bool BIAS, int OM>
__global__ void k_aggvh(const __half* __restrict__ in, const float* __restrict__ bias,
                        float* __restrict__ out, __half* __restrict__ oh) {
    constexpr int NV = C / 8;
    static_assert(NV <= SUB, "SUB too small");
    const int nodesPerWarp = 32 / SUB;
    int gwarp = (blockIdx.x * blockDim.x + threadIdx.x) >> 5;
    int lane = threadIdx.x & 31;
    int node = gwarp * nodesPerWarp + lane / SUB;
    int vl = lane % SUB;
    if (node >= NN) return;
    int p0 = g_rowptr[node], p1 = g_rowptr[node + 1];
    float acc[8] = {};
    bool active = (vl < NV);
    int p = p0;
    for (; p + 4 <= p1; p += 4) {
        int2 e0 = __ldg(&g_entries[p]);
        int2 e1 = __ldg(&g_entries[p + 1]);
        int2 e2 = __ldg(&g_entries[p + 2]);
        int2 e3 = __ldg(&g_entries[p + 3]);
        if (active) {
            int4 h0 = __ldg((const int4*)(in + (long)e0.x * C) + vl);
            int4 h1 = __ldg((const int4*)(in + (long)e1.x * C) + vl);
            int4 h2 = __ldg((const int4*)(in + (long)e2.x * C) + vl);
            int4 h3 = __ldg((const int4*)(in + (long)e3.x * C) + vl);
            accum8h(acc, h0, __int_as_float(e0.y));
            accum8h(acc, h1, __int_as_float(e1.y));
            accum8h(acc, h2, __int_as_float(e2.y));
            accum8h(acc, h3, __int_as_float(e3.y));
        }
    }
    for (; p < p1; p++) {
        int2 e = __ldg(&g_entries[p]);
        if (active) {
            int4 h = __ldg((const int4*)(in + (long)e.x * C) + vl);
            accum8h(acc, h, __int_as_float(e.y));
        }
    }
    if (active) {
        if (BIAS) {
            const float4* bp = (const float4*)bias + vl * 2;
            float4 b0 = __ldg(bp), b1 = __ldg(bp + 1);
            acc[0] += b0.x; acc[1] += b0.y; acc[2] += b0.z; acc[3] += b0.w;
            acc[4] += b1.x; acc[5] += b1.y; acc[6] += b1.z; acc[7] += b1.w;
        }
        if (ACT == 1) {
#pragma unroll
            for (int i = 0; i < 8; i++) acc[i] = fmaxf(acc[i], 0.f);
        }
        if (OM == 0) {
            float4* op = (float4*)(out + (long)node * C) + vl * 2;
            op[0] = make_float4(acc[0], acc[1], acc[2], acc[3]);
            op[1] = make_float4(acc[4], acc[5], acc[6], acc[7]);
        } else {
            __half hh[8];
#pragma unroll
            for (int i = 0; i < 8; i++) hh[i] = __float2half_rn(acc[i]);
            *((int4*)(oh + (long)node * C) + vl) = *(const int4*)hh;
        }
    }
}

// ---------------- fused eg1 -> fp16 for eg2 GEMM ----------------
__global__ void __launch_bounds__(256)
k_eg1(const float* __restrict__ x, const float* __restrict__ W,
      const float* __restrict__ Bb, __half* __restrict__ oh) {
    __shared__ float sW[480];
    __shared__ float sB[160];
    for (int i = threadIdx.x; i < 480; i += 256) sW[i] = W[i];
    for (int i = threadIdx.x; i < 160; i += 256) sB[i] = Bb[i];
    __syncthreads();
    int gwarp = (blockIdx.x * blockDim.x + threadIdx.x) >> 5;
    int lane = threadIdx.x & 31;
    int nodeBase = gwarp * 8;
    int node = nodeBase + lane / 4;
    int cl = lane & 3;
    float acc = 0.f;
    if (node < NN) {
        int p0 = g_rowptr[node], p1 = g_rowptr[node + 1];
        bool act3 = (cl < 3);
        int p = p0;
        for (; p + 4 <= p1; p += 4) {
            int2 e0 = __ldg(&g_entries[p]);
            int2 e1 = __ldg(&g_entries[p + 1]);
            int2 e2 = __ldg(&g_entries[p + 2]);
            int2 e3 = __ldg(&g_entries[p + 3]);
            if (act3) {
                float v0 = __ldg(x + (long)e0.x * 3 + cl);
                float v1 = __ldg(x + (long)e1.x * 3 + cl);
                float v2 = __ldg(x + (long)e2.x * 3 + cl);
                float v3 = __ldg(x + (long)e3.x * 3 + cl);
                acc = fmaf(__int_as_float(e0.y), v0, acc);
                acc = fmaf(__int_as_float(e1.y), v1, acc);
                acc = fmaf(__int_as_float(e2.y), v2, acc);
                acc = fmaf(__int_as_float(e3.y), v3, acc);
            }
        }
        for (; p < p1; p++) {
            int2 e = __ldg(&g_entries[p]);
            if (act3) {
                float v = __ldg(x + (long)e.x * 3 + cl);
                acc = fmaf(__int_as_float(e.y), v, acc);
            }
        }
    }
#pragma unroll
    for (int j = 0; j < 8; j++) {
        int n2 = nodeBase + j;
        float a0 = __shfl_sync(0xffffffffu, acc, j * 4 + 0);
        float a1 = __shfl_sync(0xffffffffu, acc, j * 4 + 1);
        float a2 = __shfl_sync(0xffffffffu, acc, j * 4 + 2);
        if (n2 >= NN) break;
#pragma unroll
        for (int c0 = 0; c0 < 160; c0 += 32) {
            int c = c0 + lane;
            float v = sB[c];
            v = fmaf(a0, sW[c], v);
            v = fmaf(a1, sW[160 + c], v);
            v = fmaf(a2, sW[320 + c], v);
            v = fmaxf(v, 0.f);
            oh[(long)n2 * 160 + c] = __float2half_rn(v);
        }
    }
}

// ---------------- thread-per-node dense ----------------
template <int K, int NC, int ACT, bool BIAS, bool OUTH>
__global__ void __launch_bounds__(256)
k_dense(const float* __restrict__ in, const float* __restrict__ W,
        const float* __restrict__ bias, void* __restrict__ outv) {
    __shared__ float sW[K * NC];
    __shared__ float sB[NC];
    for (int i = threadIdx.x; i < K * NC; i += 256) sW[i] = W[i];
    if (BIAS) for (int i = threadIdx.x; i < NC; i += 256) sB[i] = bias[i];
    __syncthreads();
    int n = blockIdx.x * blockDim.x + threadIdx.x;
    if (n >= NN) return;
    float acc[NC];
#pragma unroll
    for (int c = 0; c < NC; c++) acc[c] = BIAS ? sB[c] : 0.f;
    const float4* ip = (const float4*)(in + (long)n * K);
#pragma unroll
    for (int k4 = 0; k4 < K / 4; k4++) {
        float4 v = __ldg(ip + k4);
#pragma unroll
        for (int c = 0; c < NC; c++) {
            acc[c] = fmaf(v.x, sW[(k4 * 4 + 0) * NC + c], acc[c]);
            acc[c] = fmaf(v.y, sW[(k4 * 4 + 1) * NC + c], acc[c]);
            acc[c] = fmaf(v.z, sW[(k4 * 4 + 2) * NC + c], acc[c]);
            acc[c] = fmaf(v.w, sW[(k4 * 4 + 3) * NC + c], acc[c]);
        }
    }
#pragma unroll
    for (int c = 0; c < NC; c++) {
        float v = acc[c];
        if (ACT == 1) v = fmaxf(v, 0.f);
        if (OUTH) ((__half*)outv)[(long)n * NC + c] = __float2half_rn(v);
        else ((float*)outv)[(long)n * NC + c] = v;
    }
}

// ---------------- pure fp16 tensor GEMM, pre-converted operands ----------------
__device__ __forceinline__ void mma_f16(float* c, uint32_t a0, uint32_t a1,
                                        uint32_t a2, uint32_t a3,
                                        uint32_t b0, uint32_t b1) {
    asm volatile(
        "mma.sync.aligned.m16n8k16.row.col.f32.f16.f16.f32 "
        "{%0,%1,%2,%3}, {%4,%5,%6,%7}, {%8,%9}, {%0,%1,%2,%3};\n"
        : "+f"(c[0]), "+f"(c[1]), "+f"(c[2]), "+f"(c[3])
        : "r"(a0), "r"(a1), "r"(a2), "r"(a3), "r"(b0), "r"(b1));
}

#define HBM_T 128
#define HBN_T 80
#define HBK_T 32
#define HSA 40
#define HSB 40

template <int ACT, bool BIAS, int OUTM>   // OUTM: 0 f32, 1 half
__global__ void __launch_bounds__(256, 2)
k_gemm_h(const __half* __restrict__ Ah, const __half* __restrict__ Bth,
         const float* __restrict__ bias, void* __restrict__ outv,
         int M, int K, int Nc) {
    __shared__ __half sAh[HBM_T * HSA];
    __shared__ __half sBh[HBN_T * HSB];

    int tid = threadIdx.x;
    int wid = tid >> 5;
    int lane = tid & 31;
    int g = lane >> 2;
    int t = lane & 3;
    int wm = wid & 3;
    int wn = wid >> 2;
    int row0 = blockIdx.y * HBM_T;
    int col0 = blockIdx.x * HBN_T;

    float acc[2][5][4];
#pragma unroll
    for (int i = 0; i < 2; i++)
#pragma unroll
        for (int j = 0; j < 5; j++)
#pragma unroll
            for (int q = 0; q < 4; q++) acc[i][j][q] = 0.f;

    const int4 z4 = make_int4(0, 0, 0, 0);
    for (int k0 = 0; k0 < K; k0 += HBK_T) {
        // A tile: 128 rows x 32 halves = 512 int4, 2 per thread; per-group K guard
#pragma unroll
        for (int it = 0; it < 2; it++) {
            int idx = tid + it * 256;
            int m = idx >> 2, kq = idx & 3;
            int gm = row0 + m;
            int gk = k0 + kq * 8;
            bool ok = (gm < M) && (gk < K);
            *(int4*)&sAh[m * HSA + kq * 8] = ok ? *(const int4*)&Ah[(long)gm * K + gk] : z4;
        }
        // B tile: 80 rows x 32 halves = 320 int4
        {
            int idx = tid;
            if (idx < 320) {
                int n = idx >> 2, kq = idx & 3;
                int gk = k0 + kq * 8;
                bool ok = (gk < K);
                *(int4*)&sBh[n * HSB + kq * 8] = ok ? *(const int4*)&Bth[(long)(col0 + n) * K + gk] : z4;
            }
            idx = tid + 256;
            if (idx < 320) {
                int n = idx >> 2, kq = idx & 3;
                int gk = k0 + kq * 8;
                bool ok = (gk < K);
                *(int4*)&sBh[n * HSB + kq * 8] = ok ? *(const int4*)&Bth[(long)(col0 + n) * K + gk] : z4;
            }
        }
        __syncthreads();

#pragma unroll
        for (int ks = 0; ks < HBK_T; ks += 16) {
            uint32_t ah[2][4];
#pragma unroll
            for (int i = 0; i < 2; i++) {
                int r0 = wm * 32 + i * 16 + g;
                ah[i][0] = *(const uint32_t*)&sAh[r0 * HSA + ks + 2 * t];
                ah[i][1] = *(const uint32_t*)&sAh[(r0 + 8) * HSA + ks + 2 * t];
                ah[i][2] = *(const uint32_t*)&sAh[r0 * HSA + ks + 2 * t + 8];
                ah[i][3] = *(const uint32_t*)&sAh[(r0 + 8) * HSA + ks + 2 * t + 8];
            }
#pragma unroll
            for (int j = 0; j < 5; j++) {
                int c = wn * 40 + j * 8 + g;
                uint32_t bh0 = *(const uint32_t*)&sBh[c * HSB + ks + 2 * t];
                uint32_t bh1 = *(const uint32_t*)&sBh[c * HSB + ks + 2 * t + 8];
#pragma unroll
                for (int i = 0; i < 2; i++)
                    mma_f16(acc[i][j], ah[i][0], ah[i][1], ah[i][2], ah[i][3], bh0, bh1);
            }
        }
        __syncthreads();
    }

#pragma unroll
    for (int i = 0; i < 2; i++) {
        int rbase = row0 + wm * 32 + i * 16 + g;
#pragma unroll
        for (int j = 0; j < 5; j++) {
            int cbase = col0 + wn * 40 + j * 8 + t * 2;
#pragma unroll
            for (int q = 0; q < 4; q++) {
                int gm = rbase + ((q >= 2) ? 8 : 0);
                int gn = cbase + (q & 1);
                if (gm < M && gn < Nc) {
                    float v = acc[i][j][q];
                    if (BIAS) v += bias[gn];
                    if (ACT == 1) v = fmaxf(v, 0.f);
                    if (OUTM == 1) ((__half*)outv)[(long)gm * Nc + gn] = __float2half_rn(v);
                    else ((float*)outv)[(long)gm * Nc + gn] = v;
                }
            }
        }
    }
}

// ---------------- fused dense chain ----------------
__global__ void __launch_bounds__(256)
k_chain(const float* __restrict__ in, float* __restrict__ out,
        const float* __restrict__ w1, const float* __restrict__ b1,
        const float* __restrict__ w2, const float* __restrict__ b2,
        const float* __restrict__ w3, const float* __restrict__ b3,
        const float* __restrict__ w4, const float* __restrict__ b4) {
    __shared__ float sw1[200], sb1[10], sw2[30], sb2[3], sw3[30], sb3[10], sw4[200], sb4[20];
    int tid = threadIdx.x;
    for (int i = tid; i < 200; i += 256) sw1[i] = w1[i];
    for (int i = tid; i < 10; i += 256) sb1[i] = b1[i];
    for (int i = tid; i < 30; i += 256) sw2[i] = w2[i];
    for (int i = tid; i < 3; i += 256) sb2[i] = b2[i];
    for (int i = tid; i < 30; i += 256) sw3[i] = w3[i];
    for (int i = tid; i < 10; i += 256) sb3[i] = b3[i];
    for (int i = tid; i < 200; i += 256) sw4[i] = w4[i];
    for (int i = tid; i < 20; i += 256) sb4[i] = b4[i];
    __syncthreads();

    int n = blockIdx.x * blockDim.x + tid;
    if (n >= NN) return;
    float h0[20];
    const float4* ip = (const float4*)(in + (long)n * 20);
#pragma unroll
    for (int i = 0; i < 5; i++) {
        float4 v = __ldg(ip + i);
        h0[i * 4 + 0] = v.x; h0[i * 4 + 1] = v.y; h0[i * 4 + 2] = v.z; h0[i * 4 + 3] = v.w;
    }
    float h1[10];
#pragma unroll
    for (int j = 0; j < 10; j++) {
        float s = sb1[j];
#pragma unroll
        for (int i = 0; i < 20; i++) s = fmaf(h0[i], sw1[i * 10 + j], s);
        h1[j] = fmaxf(s, 0.f);
    }
    float z[3];
#pragma unroll
    for (int j = 0; j < 3; j++) {
        float s = sb2[j];
#pragma unroll
        for (int i = 0; i < 10; i++) s = fmaf(h1[i], sw2[i * 3 + j], s);
        z[j] = s;
    }
    float h2[10];
#pragma unroll
    for (int j = 0; j < 10; j++) {
        float s = sb3[j];
#pragma unroll
        for (int i = 0; i < 3; i++) s = fmaf(z[i], sw3[i * 10 + j], s);
        h2[j] = fmaxf(s, 0.f);
    }
    float* op = out + (long)n * 20;
#pragma unroll
    for (int j = 0; j < 20; j++) {
        float s = sb4[j];
#pragma unroll
        for (int i = 0; i < 10; i++) s = fmaf(h2[i], sw4[i * 20 + j], s);
        op[j] = fmaxf(s, 0.f);
    }
}

// ---------------- driver ----------------
template <int ACT, bool BIAS, int OUTM>
static void gemm_h(const __half* Ah, const __half* Bth, const float* b, void* o,
                   int K, int Nc) {
    dim3 g(cdiv(Nc, HBN_T), cdiv(NN, HBM_T));
    k_gemm_h<ACT, BIAS, OUTM><<<g, 256>>>(Ah, Bth, b, o, NN, K, Nc);
}

extern "C" void kernel_launch(void* const* d_in, const int* in_sizes, int n_in,
                              void* d_out, int out_size) {
    const float* x = (const float*)d_in[0];
    const int* ei = (const int*)d_in[1];
    const int* src = ei;
    const int* dst = ei + NE;
    const float* W[12];
    const float* B[12];
    for (int i = 0; i < 12; i++) {
        W[i] = (const float*)d_in[2 + 2 * i];
        B[i] = (const float*)d_in[3 + 2 * i];
    }
    float* bufA; cudaGetSymbolAddress((void**)&bufA, g_bufA);
    float* bufB; cudaGetSymbolAddress((void**)&bufB, g_bufB);
    __half* bufH; cudaGetSymbolAddress((void**)&bufH, g_bufH);
    __half* ah; cudaGetSymbolAddress((void**)&ah, g_ah);
    __half* wth; cudaGetSymbolAddress((void**)&wth, g_wth);
    float* outp = (float*)d_out;

    const int NB = cdiv(NN, 1024);
    // weight conversion (single launch)
    k_wconv_all<<<cdiv(32000, 256), 256>>>(W[1], W[2], W[9], W[10]);
    // CSR build
    k_init_cnt<<<cdiv(NN, 256), 256>>>();
    k_count<<<cdiv(NE, 256), 256>>>(dst);
    k_scan1<<<NB, 1024>>>();
    k_scan2<<<1, 128>>>(NB);
    k_scan3<<<NB, 1024>>>();
    k_self<<<cdiv(NN, 256), 256>>>();
    k_edges<<<cdiv(NE, 256), 256>>>(src, dst);

    const int TPB = 256;
    int blocks16 = cdiv(cdiv(NN, 2) * 32, TPB);
    int blocks8  = cdiv(cdiv(NN, 4) * 32, TPB);
    int blocks4  = cdiv(cdiv(NN, 8) * 32, TPB);
    int blocksN  = cdiv(NN, TPB);

    // encoder
    k_eg1<<<blocks4, TPB>>>(x, W[0], B[0], ah);                                     // agg+eg1 -> fp16
    gemm_h<0, false, 1>(ah, wth + WOFF_EG2, nullptr, bufH, 160, 80);                // eg2 matmul
    k_aggvh<80, 16, 1, true, 1><<<blocks16, TPB>>>(bufH, B[1], nullptr, ah);        // eg2 agg -> fp16
    gemm_h<0, false, 1>(ah, wth + WOFF_EG3, nullptr, bufH, 80, 40);                 // eg3 matmul
    k_aggvh<40, 8, 1, true, 0><<<blocks8, TPB>>>(bufH, B[2], bufB, nullptr);        // eg3 agg
    k_dense<40, 20, 0, false, false><<<blocksN, TPB>>>(bufB, W[3], nullptr, bufA);  // eg4 matmul
    k_aggv<20, 8, 1, true><<<blocks8, TPB>>>(bufA, B[3], bufB);                     // eg4 agg
    // latent dense chain
    k_chain<<<blocksN, TPB>>>(bufB, bufA, W[4], B[4], W[5], B[5], W[6], B[6], W[7], B[7]);
    // decoder
    k_aggv<20, 8, 0, false><<<blocks8, TPB>>>(bufA, nullptr, bufB);                 // dg1 agg
    k_dense<20, 40, 1, true, true><<<blocksN, TPB>>>(bufB, W[8], B[8], bufH);       // dg1 -> fp16
    k_aggvh<40, 8, 0, false, 1><<<blocks8, TPB>>>(bufH, nullptr, nullptr, ah);      // dg2 agg -> fp16
    gemm_h<1, true, 1>(ah, wth + WOFF_DG2, B[9], bufH, 40, 80);                     // dg2
    k_aggvh<80, 16, 0, false, 1><<<blocks16, TPB>>>(bufH, nullptr, nullptr, ah);    // dg3 agg -> fp16
    gemm_h<1, true, 0>(ah, wth + WOFF_DG3, B[10], bufA, 80, 160);                   // dg3
    k_dense<160, 3, 0, false, false><<<blocksN, TPB>>>(bufA, W[11], nullptr, bufB); // dg4 matmul
    k_agg3<2, true><<<blocks4, TPB>>>(bufB, B[11], outp);                           // dg4 agg+tanh
}

// round 10
// speedup vs baseline: 1.6931x; 1.0698x over previous
#include <cuda_runtime.h>
#include <cuda_fp16.h>
#include <cuda_bf16.h>
#include <cstdint>

#define NN 100000
#define NE 1600000
#define NTOT (NE + NN)

// ---------------- scratch (device globals: allocation-free) ----------------
__device__ float  g_bufA[NN * 160];
__device__ float  g_bufB[NN * 160];
__device__ __align__(16) __half g_bufH[NN * 80];
__device__ __align__(16) __half g_ah[NN * 160];    // GEMM A operand (fp16)
__device__ __align__(16) __half g_ah2[NN * 160];   // dg3 fp16 output
__device__ __align__(16) __half g_wth[32000];      // transposed weights [n*K+k] fp16
__device__ int    g_cnt[NN];
__device__ float  g_dis[NN];
__device__ int    g_rowptr[NN + 1];
__device__ int    g_fill[NN];
__device__ int2   g_entries[NTOT];
__device__ int    g_bsums[128];

static inline int cdiv(int a, int b) { return (a + b - 1) / b; }

#define WOFF_EG2 0        // W1: 160x80  -> 12800
#define WOFF_EG3 12800    // W2: 80x40   -> 3200
#define WOFF_DG2 16000    // W9: 40x80   -> 3200
#define WOFF_DG3 19200    // W10: 80x160 -> 12800

// ---------------- CSR build ----------------
__global__ void k_init_cnt() {
    int i = blockIdx.x * blockDim.x + threadIdx.x;
    if (i < NN) g_cnt[i] = 1;
}
__global__ void k_count(const int* __restrict__ dst) {
    int e = blockIdx.x * blockDim.x + threadIdx.x;
    if (e < NE) atomicAdd(&g_cnt[dst[e]], 1);
}
__global__ void k_scan1() {
    __shared__ int s[1024];
    int i = blockIdx.x * 1024 + threadIdx.x;
    int v = (i < NN) ? g_cnt[i] : 0;
    if (i < NN) g_dis[i] = rsqrtf((float)v);
    s[threadIdx.x] = v;
    __syncthreads();
    for (int d = 1; d < 1024; d <<= 1) {
        int t = (threadIdx.x >= d) ? s[threadIdx.x - d] : 0;
        __syncthreads();
        s[threadIdx.x] += t;
        __syncthreads();
    }
    if (i < NN) g_rowptr[i + 1] = s[threadIdx.x];
    if (threadIdx.x == 1023) g_bsums[blockIdx.x] = s[1023];
}
__global__ void k_scan2(int nb) {
    __shared__ int s[128];
    int v = (threadIdx.x < nb) ? g_bsums[threadIdx.x] : 0;
    s[threadIdx.x] = v;
    __syncthreads();
    for (int d = 1; d < 128; d <<= 1) {
        int t = (threadIdx.x >= d) ? s[threadIdx.x - d] : 0;
        __syncthreads();
        s[threadIdx.x] += t;
        __syncthreads();
    }
    if (threadIdx.x < nb) g_bsums[threadIdx.x] = s[threadIdx.x] - v;
}
__global__ void k_scan3() {
    int i = blockIdx.x * 1024 + threadIdx.x;
    if (i < NN) g_rowptr[i + 1] += g_bsums[blockIdx.x];
    if (i == 0) g_rowptr[0] = 0;
}
__global__ void k_self() {
    int i = blockIdx.x * blockDim.x + threadIdx.x;
    if (i < NN) {
        int p = g_rowptr[i];
        float d = g_dis[i];
        g_entries[p] = make_int2(i, __float_as_int(d * d));
        g_fill[i] = p + 1;
    }
}
__global__ void k_edges(const int* __restrict__ src, const int* __restrict__ dst) {
    int e = blockIdx.x * blockDim.x + threadIdx.x;
    if (e < NE) {
        int s = src[e], d = dst[e];
        int p = atomicAdd(&g_fill[d], 1);
        g_entries[p] = make_int2(s, __float_as_int(g_dis[s] * g_dis[d]));
    }
}

// ---------------- all-weights convert+transpose (single launch) ----------------
__global__ void k_wconv_all(const float* __restrict__ W1, const float* __restrict__ W2,
                            const float* __restrict__ W9, const float* __restrict__ W10) {
    int idx = blockIdx.x * blockDim.x + threadIdx.x;
    if (idx >= 32000) return;
    const float* W; int K, Nc, off, li;
    if (idx < 12800)      { W = W1;  K = 160; Nc = 80;  off = WOFF_EG2; li = idx; }
    else if (idx < 16000) { W = W2;  K = 80;  Nc = 40;  off = WOFF_EG3; li = idx - 12800; }
    else if (idx < 19200) { W = W9;  K = 40;  Nc = 80;  off = WOFF_DG2; li = idx - 16000; }
    else                  { W = W10; K = 80;  Nc = 160; off = WOFF_DG3; li = idx - 19200; }
    int k = li / Nc, n = li - k * Nc;
    g_wth[off + n * K + k] = __float2half_rn(W[li]);
}

// ---------------- scalar aggregation (C=3) ----------------
template <int ACT, bool BIAS, typename TIN>
__global__ void k_agg3(const TIN* __restrict__ in, const float* __restrict__ bias,
                       float* __restrict__ out) {
    int gwarp = (blockIdx.x * blockDim.x + threadIdx.x) >> 5;
    int lane = threadIdx.x & 31;
    int node = gwarp * 8 + lane / 4;
    int cl = lane & 3;
    if (node >= NN) return;
    int p0 = g_rowptr[node], p1 = g_rowptr[node + 1];
    float acc = 0.f;
    bool act3 = (cl < 3);
    int p = p0;
    for (; p + 4 <= p1; p += 4) {
        int2 e0 = __ldg(&g_entries[p]);
        int2 e1 = __ldg(&g_entries[p + 1]);
        int2 e2 = __ldg(&g_entries[p + 2]);
        int2 e3 = __ldg(&g_entries[p + 3]);
        if (act3) {
            float v0 = (float)__ldg(in + (long)e0.x * 3 + cl);
            float v1 = (float)__ldg(in + (long)e1.x * 3 + cl);
            float v2 = (float)__ldg(in + (long)e2.x * 3 + cl);
            float v3 = (float)__ldg(in + (long)e3.x * 3 + cl);
            acc = fmaf(__int_as_float(e0.y), v0, acc);
            acc = fmaf(__int_as_float(e1.y), v1, acc);
            acc = fmaf(__int_as_float(e2.y), v2, acc);
            acc = fmaf(__int_as_float(e3.y), v3, acc);
        }
    }
    for (; p < p1; p++) {
        int2 e = __ldg(&g_entries[p]);
        if (act3) {
            float v = (float)__ldg(in + (long)e.x * 3 + cl);
            acc = fmaf(__int_as_float(e.y), v, acc);
        }
    }
    if (act3) {
        float v = acc;
        if (BIAS) v += bias[cl];
        if (ACT == 1) v = fmaxf(v, 0.f);
        if (ACT == 2) v = tanhf(v);
        out[(long)node * 3 + cl] = v;
    }
}

// ---------------- fp32 vectorized aggregation (SUB = C/4 exactly for full lanes) ----------------
template <int C, int SUB, int ACT, bool BIAS>
__global__ void k_aggv(const float* __restrict__ in, const float* __restrict__ bias,
                       float* __restrict__ out) {
    constexpr int NV = C / 4;
    static_assert(NV <= SUB, "SUB too small");
    constexpr int NPW = 32 / SUB;
    int gwarp = (blockIdx.x * blockDim.x + threadIdx.x) >> 5;
    int lane = threadIdx.x & 31;
    int sg = lane / SUB;
    if (sg >= NPW) return;
    int node = gwarp * NPW + sg;
    int vl = lane % SUB;
    if (node >= NN) return;
    int p0 = g_rowptr[node], p1 = g_rowptr[node + 1];
    float4 acc = make_float4(0.f, 0.f, 0.f, 0.f);
    bool active = (vl < NV);
    int p = p0;
    for (; p + 4 <= p1; p += 4) {
        int2 e0 = __ldg(&g_entries[p]);
        int2 e1 = __ldg(&g_entries[p + 1]);
        int2 e2 = __ldg(&g_entries[p + 2]);
        int2 e3 = __ldg(&g_entries[p + 3]);
        if (active) {
            float4 v0 = __ldg((const float4*)(in + (long)e0.x * C) + vl);
            float4 v1 = __ldg((const float4*)(in + (long)e1.x * C) + vl);
            float4 v2 = __ldg((const float4*)(in + (long)e2.x * C) + vl);
            float4 v3 = __ldg((const float4*)(in + (long)e3.x * C) + vl);
            float w0 = __int_as_float(e0.y), w1 = __int_as_float(e1.y);
            float w2 = __int_as_float(e2.y), w3 = __int_as_float(e3.y);
            acc.x = fmaf(w0, v0.x, acc.x); acc.y = fmaf(w0, v0.y, acc.y);
            acc.z = fmaf(w0, v0.z, acc.z); acc.w = fmaf(w0, v0.w, acc.w);
            acc.x = fmaf(w1, v1.x, acc.x); acc.y = fmaf(w1, v1.y, acc.y);
            acc.z = fmaf(w1, v1.z, acc.z); acc.w = fmaf(w1, v1.w, acc.w);
            acc.x = fmaf(w2, v2.x, acc.x); acc.y = fmaf(w2, v2.y, acc.y);
            acc.z = fmaf(w2, v2.z, acc.z); acc.w = fmaf(w2, v2.w, acc.w);
            acc.x = fmaf(w3, v3.x, acc.x); acc.y = fmaf(w3, v3.y, acc.y);
            acc.z = fmaf(w3, v3.z, acc.z); acc.w = fmaf(w3, v3.w, acc.w);
        }
    }
    for (; p < p1; p++) {
        int2 e = __ldg(&g_entries[p]);
        if (active) {
            float w = __int_as_float(e.y);
            float4 v = __ldg((const float4*)(in + (long)e.x * C) + vl);
            acc.x = fmaf(w, v.x, acc.x); acc.y = fmaf(w, v.y, acc.y);
            acc.z = fmaf(w, v.z, acc.z); acc.w = fmaf(w, v.w, acc.w);
        }
    }
    if (active) {
        if (BIAS) {
            float4 bv = __ldg((const float4*)bias + vl);
            acc.x += bv.x; acc.y += bv.y; acc.z += bv.z; acc.w += bv.w;
        }
        if (ACT == 1) {
            acc.x = fmaxf(acc.x, 0.f); acc.y = fmaxf(acc.y, 0.f);
            acc.z = fmaxf(acc.z, 0.f); acc.w = fmaxf(acc.w, 0.f);
        }
        *((float4*)(out + (long)node * C) + vl) = acc;
    }
}

// ---------------- fp16-input aggregation; OM: 0=f32 out, 1=fp16 out ----------------
__device__ __forceinline__ void accum8h(float* acc, int4 h, float w) {
    const __half2* hp = (const __half2*)&h;
#pragma unroll
    for (int i = 0; i < 4; i++) {
        float2 f = __half22float2(hp[i]);
        acc[2 * i]     = fmaf(w, f.x, acc[2 * i]);
        acc[2 * i + 1] = fmaf(w, f.y, acc[2 * i + 1]);
    }
}

template <int C, int SUB, int ACT, bool BIAS, int OM>
__global__ void k_aggvh(const __half* __restrict__ in, const float* __restrict__ bias,
                        float* __restrict__ out, __half* __restrict__ oh) {
    constexpr int NV = C / 8;
    static_assert(NV <= SUB, "SUB too small");
    constexpr int NPW = 32 / SUB;
    int gwarp = (blockIdx.x * blockDim.x + threadIdx.x) >> 5;
    int lane = threadIdx.x & 31;
    int sg = lane / SUB;
    if (sg >= NPW) return;
    int node = gwarp * NPW + sg;
    int vl = lane % SUB;
    if (node >= NN) return;
    int p0 = g_rowptr[node], p1 = g_rowptr[node + 1];
    float acc[8] = {};
    bool active = (vl < NV);
    int p = p0;
    for (; p + 4 <= p1; p += 4) {
        int2 e0 = __ldg(&g_entries[p]);
        int2 e1 = __ldg(&g_entries[p + 1]);
        int2 e2 = __ldg(&g_entries[p + 2]);
        int2 e3 = __ldg(&g_entries[p + 3]);
        if (active) {
            int4 h0 = __ldg((const int4*)(in + (long)e0.x * C) + vl);
            int4 h1 = __ldg((const int4*)(in + (long)e1.x * C) + vl);
            int4 h2 = __ldg((const int4*)(in + (long)e2.x * C) + vl);
            int4 h3 = __ldg((const int4*)(in + (long)e3.x * C) + vl);
            accum8h(acc, h0, __int_as_float(e0.y));
            accum8h(acc, h1, __int_as_float(e1.y));
            accum8h(acc, h2, __int_as_float(e2.y));
            accum8h(acc, h3, __int_as_float(e3.y));
        }
    }
    for (; p < p1; p++) {
        int2 e = __ldg(&g_entries[p]);
        if (active) {
            int4 h = __ldg((const int4*)(in + (long)e.x * C) + vl);
            accum8h(acc, h, __int_as_float(e.y));
        }
    }
    if (active) {
        if (BIAS) {
            const float4* bp = (const float4*)bias + vl * 2;
            float4 b0 = __ldg(bp), b1 = __ldg(bp + 1);
            acc[0] += b0.x; acc[1] += b0.y; acc[2] += b0.z; acc[3] += b0.w;
            acc[4] += b1.x; acc[5] += b1.y; acc[6] += b1.z; acc[7] += b1.w;
        }
        if (ACT == 1) {
#pragma unroll
            for (int i = 0; i < 8; i++) acc[i] = fmaxf(acc[i], 0.f);
        }
        if (OM == 0) {
            float4* op = (float4*)(out + (long)node * C) + vl * 2;
            op[0] = make_float4(acc[0], acc[1], acc[2], acc[3]);
            op[1] = make_float4(acc[4], acc[5], acc[6], acc[7]);
        } else {
            __half hh[8];
#pragma unroll
            for (int i = 0; i < 8; i++) hh[i] = __float2half_rn(acc[i]);
            *((int4*)(oh + (long)node * C) + vl) = *(const int4*)hh;
        }
    }
}

// ---------------- fused eg1 -> fp16 for eg2 GEMM ----------------
__global__ void __launch_bounds__(256)
k_eg1(const float* __restrict__ x, const float* __restrict__ W,
      const float* __restrict__ Bb, __half* __restrict__ oh) {
    __shared__ float sW[480];
    __shared__ float sB[160];
    for (int i = threadIdx.x; i < 480; i += 256) sW[i] = W[i];
    for (int i = threadIdx.x; i < 160; i += 256) sB[i] = Bb[i];
    __syncthreads();
    int gwarp = (blockIdx.x * blockDim.x + threadIdx.x) >> 5;
    int lane = threadIdx.x & 31;
    int nodeBase = gwarp * 8;
    int node = nodeBase + lane / 4;
    int cl = lane & 3;
    float acc = 0.f;
    if (node < NN) {
        int p0 = g_rowptr[node], p1 = g_rowptr[node + 1];
        bool act3 = (cl < 3);
        int p = p0;
        for (; p + 4 <= p1; p += 4) {
            int2 e0 = __ldg(&g_entries[p]);
            int2 e1 = __ldg(&g_entries[p + 1]);
            int2 e2 = __ldg(&g_entries[p + 2]);
            int2 e3 = __ldg(&g_entries[p + 3]);
            if (act3) {
                float v0 = __ldg(x + (long)e0.x * 3 + cl);
                float v1 = __ldg(x + (long)e1.x * 3 + cl);
                float v2 = __ldg(x + (long)e2.x * 3 + cl);
                float v3 = __ldg(x + (long)e3.x * 3 + cl);
                acc = fmaf(__int_as_float(e0.y), v0, acc);
                acc = fmaf(__int_as_float(e1.y), v1, acc);
                acc = fmaf(__int_as_float(e2.y), v2, acc);
                acc = fmaf(__int_as_float(e3.y), v3, acc);
            }
        }
        for (; p < p1; p++) {
            int2 e = __ldg(&g_entries[p]);
            if (act3) {
                float v = __ldg(x + (long)e.x * 3 + cl);
                acc = fmaf(__int_as_float(e.y), v, acc);
            }
        }
    }
#pragma unroll
    for (int j = 0; j < 8; j++) {
        int n2 = nodeBase + j;
        float a0 = __shfl_sync(0xffffffffu, acc, j * 4 + 0);
        float a1 = __shfl_sync(0xffffffffu, acc, j * 4 + 1);
        float a2 = __shfl_sync(0xffffffffu, acc, j * 4 + 2);
        if (n2 >= NN) break;
#pragma unroll
        for (int c0 = 0; c0 < 160; c0 += 32) {
            int c = c0 + lane;
            float v = sB[c];
            v = fmaf(a0, sW[c], v);
            v = fmaf(a1, sW[160 + c], v);
            v = fmaf(a2, sW[320 + c], v);
            v = fmaxf(v, 0.f);
            oh[(long)n2 * 160 + c] = __float2half_rn(v);
        }
    }
}

// ---------------- thread-per-node dense (fp32 input) ----------------
template <int K, int NC, int ACT, bool BIAS, bool OUTH>
__global__ void __launch_bounds__(256)
k_dense(const float* __restrict__ in, const float* __restrict__ W,
        const float* __restrict__ bias, void* __restrict__ outv) {
    __shared__ float sW[K * NC];
    __shared__ float sB[NC];
    for (int i = threadIdx.x; i < K * NC; i += 256) sW[i] = W[i];
    if (BIAS) for (int i = threadIdx.x; i < NC; i += 256) sB[i] = bias[i];
    __syncthreads();
    int n = blockIdx.x * blockDim.x + threadIdx.x;
    if (n >= NN) return;
    float acc[NC];
#pragma unroll
    for (int c = 0; c < NC; c++) acc[c] = BIAS ? sB[c] : 0.f;
    const float4* ip = (const float4*)(in + (long)n * K);
#pragma unroll
    for (int k4 = 0; k4 < K / 4; k4++) {
        float4 v = __ldg(ip + k4);
#pragma unroll
        for (int c = 0; c < NC; c++) {
            acc[c] = fmaf(v.x, sW[(k4 * 4 + 0) * NC + c], acc[c]);
            acc[c] = fmaf(v.y, sW[(k4 * 4 + 1) * NC + c], acc[c]);
            acc[c] = fmaf(v.z, sW[(k4 * 4 + 2) * NC + c], acc[c]);
            acc[c] = fmaf(v.w, sW[(k4 * 4 + 3) * NC + c], acc[c]);
        }
    }
#pragma unroll
    for (int c = 0; c < NC; c++) {
        float v = acc[c];
        if (ACT == 1) v = fmaxf(v, 0.f);
        if (OUTH) ((__half*)outv)[(long)n * NC + c] = __float2half_rn(v);
        else ((float*)outv)[(long)n * NC + c] = v;
    }
}

// ---------------- thread-per-node dense (fp16 input) ----------------
template <int K, int NC, int ACT, bool BIAS>
__global__ void __launch_bounds__(256)
k_dense_h(const __half* __restrict__ in, const float* __restrict__ W,
          const float* __restrict__ bias, float* __restrict__ out) {
    __shared__ float sW[K * NC];
    __shared__ float sB[NC];
    for (int i = threadIdx.x; i < K * NC; i += 256) sW[i] = W[i];
    if (BIAS) for (int i = threadIdx.x; i < NC; i += 256) sB[i] = bias[i];
    __syncthreads();
    int n = blockIdx.x * blockDim.x + threadIdx.x;
    if (n >= NN) return;
    float acc[NC];
#pragma unroll
    for (int c = 0; c < NC; c++) acc[c] = BIAS ? sB[c] : 0.f;
    const int4* ip = (const int4*)(in + (long)n * K);
#pragma unroll
    for (int k8 = 0; k8 < K / 8; k8++) {
        int4 hv = __ldg(ip + k8);
        const __half2* hp = (const __half2*)&hv;
#pragma unroll
        for (int q = 0; q < 4; q++) {
            float2 f = __half22float2(hp[q]);
            int kk = k8 * 8 + q * 2;
#pragma unroll
            for (int c = 0; c < NC; c++) {
                acc[c] = fmaf(f.x, sW[kk * NC + c], acc[c]);
                acc[c] = fmaf(f.y, sW[(kk + 1) * NC + c], acc[c]);
            }
        }
    }
#pragma unroll
    for (int c = 0; c < NC; c++) {
        float v = acc[c];
        if (ACT == 1) v = fmaxf(v, 0.f);
        out[(long)n * NC + c] = v;
    }
}

// ---------------- pure fp16 tensor GEMM, pre-converted operands ----------------
__device__ __forceinline__ void mma_f16(float* c, uint32_t a0, uint32_t a1,
                                        uint32_t a2, uint32_t a3,
                                        uint32_t b0, uint32_t b1) {
    asm volatile(
        "mma.sync.aligned.m16n8k16.row.col.f32.f16.f16.f32 "
        "{%0,%1,%2,%3}, {%4,%5,%6,%7}, {%8,%9}, {%0,%1,%2,%3};\n"
        : "+f"(c[0]), "+f"(c[1]), "+f"(c[2]), "+f"(c[3])
        : "r"(a0), "r"(a1), "r"(a2), "r"(a3), "r"(b0), "r"(b1));
}

#define HBM_T 128
#define HBN_T 80
#define HBK_T 32
#define HSA 40
#define HSB 40

template <int ACT, bool BIAS, int OUTM>   // OUTM: 0 f32, 1 half
__global__ void __launch_bounds__(256, 2)
k_gemm_h(const __half* __restrict__ Ah, const __half* __restrict__ Bth,
         const float* __restrict__ bias, void* __restrict__ outv,
         int M, int K, int Nc) {
    __shared__ __half sAh[HBM_T * HSA];
    __shared__ __half sBh[HBN_T * HSB];

    int tid = threadIdx.x;
    int wid = tid >> 5;
    int lane = tid & 31;
    int g = lane >> 2;
    int t = lane & 3;
    int wm = wid & 3;
    int wn = wid >> 2;
    int row0 = blockIdx.y * HBM_T;
    int col0 = blockIdx.x * HBN_T;

    float acc[2][5][4];
#pragma unroll
    for (int i = 0; i < 2; i++)
#pragma unroll
        for (int j = 0; j < 5; j++)
#pragma unroll
            for (int q = 0; q < 4; q++) acc[i][j][q] = 0.f;

    const int4 z4 = make_int4(0, 0, 0, 0);
    for (int k0 = 0; k0 < K; k0 += HBK_T) {
#pragma unroll
        for (int it = 0; it < 2; it++) {
            int idx = tid + it * 256;
            int m = idx >> 2, kq = idx & 3;
            int gm = row0 + m;
            int gk = k0 + kq * 8;
            bool ok = (gm < M) && (gk < K);
            *(int4*)&sAh[m * HSA + kq * 8] = ok ? *(const int4*)&Ah[(long)gm * K + gk] : z4;
        }
        {
            int idx = tid;
            if (idx < 320) {
                int n = idx >> 2, kq = idx & 3;
                int gk = k0 + kq * 8;
                bool ok = (gk < K);
                *(int4*)&sBh[n * HSB + kq * 8] = ok ? *(const int4*)&Bth[(long)(col0 + n) * K + gk] : z4;
            }
            idx = tid + 256;
            if (idx < 320) {
                int n = idx >> 2, kq = idx & 3;
                int gk = k0 + kq * 8;
                bool ok = (gk < K);
                *(int4*)&sBh[n * HSB + kq * 8] = ok ? *(const int4*)&Bth[(long)(col0 + n) * K + gk] : z4;
            }
        }
        __syncthreads();

#pragma unroll
        for (int ks = 0; ks < HBK_T; ks += 16) {
            uint32_t ah[2][4];
#pragma unroll
            for (int i = 0; i < 2; i++) {
                int r0 = wm * 32 + i * 16 + g;
                ah[i][0] = *(const uint32_t*)&sAh[r0 * HSA + ks + 2 * t];
                ah[i][1] = *(const uint32_t*)&sAh[(r0 + 8) * HSA + ks + 2 * t];
                ah[i][2] = *(const uint32_t*)&sAh[r0 * HSA + ks + 2 * t + 8];
                ah[i][3] = *(const uint32_t*)&sAh[(r0 + 8) * HSA + ks + 2 * t + 8];
            }
#pragma unroll
            for (int j = 0; j < 5; j++) {
                int c = wn * 40 + j * 8 + g;
                uint32_t bh0 = *(const uint32_t*)&sBh[c * HSB + ks + 2 * t];
                uint32_t bh1 = *(const uint32_t*)&sBh[c * HSB + ks + 2 * t + 8];
#pragma unroll
                for (int i = 0; i < 2; i++)
                    mma_f16(acc[i][j], ah[i][0], ah[i][1], ah[i][2], ah[i][3], bh0, bh1);
            }
        }
        __syncthreads();
    }

#pragma unroll
    for (int i = 0; i < 2; i++) {
        int rbase = row0 + wm * 32 + i * 16 + g;
#pragma unroll
        for (int j = 0; j < 5; j++) {
            int cbase = col0 + wn * 40 + j * 8 + t * 2;
#pragma unroll
            for (int q = 0; q < 4; q++) {
                int gm = rbase + ((q >= 2) ? 8 : 0);
                int gn = cbase + (q & 1);
                if (gm < M && gn < Nc) {
                    float v = acc[i][j][q];
                    if (BIAS) v += bias[gn];
                    if (ACT == 1) v = fmaxf(v, 0.f);
                    if (OUTM == 1) ((__half*)outv)[(long)gm * Nc + gn] = __float2half_rn(v);
                    else ((float*)outv)[(long)gm * Nc + gn] = v;
                }
            }
        }
    }
}

// ---------------- fused dense chain ----------------
__global__ void __launch_bounds__(256)
k_chain(const float* __restrict__ in, float* __restrict__ out,
        const float* __restrict__ w1, const float* __restrict__ b1,
        const float* __restrict__ w2, const float* __restrict__ b2,
        const float* __restrict__ w3, const float* __restrict__ b3,
        const float* __restrict__ w4, const float* __restrict__ b4) {
    __shared__ float sw1[200], sb1[10], sw2[30], sb2[3], sw3[30], sb3[10], sw4[200], sb4[20];
    int tid = threadIdx.x;
    for (int i = tid; i < 200; i += 256) sw1[i] = w1[i];
    for (int i = tid; i < 10; i += 256) sb1[i] = b1[i];
    for (int i = tid; i < 30; i += 256) sw2[i] = w2[i];
    for (int i = tid; i < 3; i += 256) sb2[i] = b2[i];
    for (int i = tid; i < 30; i += 256) sw3[i] = w3[i];
    for (int i = tid; i < 10; i += 256) sb3[i] = b3[i];
    for (int i = tid; i < 200; i += 256) sw4[i] = w4[i];
    for (int i = tid; i < 20; i += 256) sb4[i] = b4[i];
    __syncthreads();

    int n = blockIdx.x * blockDim.x + tid;
    if (n >= NN) return;
    float h0[20];
    const float4* ip = (const float4*)(in + (long)n * 20);
#pragma unroll
    for (int i = 0; i < 5; i++) {
        float4 v = __ldg(ip + i);
        h0[i * 4 + 0] = v.x; h0[i * 4 + 1] = v.y; h0[i * 4 + 2] = v.z; h0[i * 4 + 3] = v.w;
    }
    float h1[10];
#pragma unroll
    for (int j = 0; j < 10; j++) {
        float s = sb1[j];
#pragma unroll
        for (int i = 0; i < 20; i++) s = fmaf(h0[i], sw1[i * 10 + j], s);
        h1[j] = fmaxf(s, 0.f);
    }
    float z[3];
#pragma unroll
    for (int j = 0; j < 3; j++) {
        float s = sb2[j];
#pragma unroll
        for (int i = 0; i < 10; i++) s = fmaf(h1[i], sw2[i * 3 + j], s);
        z[j] = s;
    }
    float h2[10];
#pragma unroll
    for (int j = 0; j < 10; j++) {
        float s = sb3[j];
#pragma unroll
        for (int i = 0; i < 3; i++) s = fmaf(z[i], sw3[i * 10 + j], s);
        h2[j] = fmaxf(s, 0.f);
    }
    float* op = out + (long)n * 20;
#pragma unroll
    for (int j = 0; j < 20; j++) {
        float s = sb4[j];
#pragma unroll
        for (int i = 0; i < 10; i++) s = fmaf(h2[i], sw4[i * 20 + j], s);
        op[j] = fmaxf(s, 0.f);
    }
}

// ---------------- driver ----------------
template <int ACT, bool BIAS, int OUTM>
static void gemm_h(const __half* Ah, const __half* Bth, const float* b, void* o,
                   int K, int Nc) {
    dim3 g(cdiv(Nc, HBN_T), cdiv(NN, HBM_T));
    k_gemm_h<ACT, BIAS, OUTM><<<g, 256>>>(Ah, Bth, b, o, NN, K, Nc);
}

extern "C" void kernel_launch(void* const* d_in, const int* in_sizes, int n_in,
                              void* d_out, int out_size) {
    const float* x = (const float*)d_in[0];
    const int* ei = (const int*)d_in[1];
    const int* src = ei;
    const int* dst = ei + NE;
    const float* W[12];
    const float* B[12];
    for (int i = 0; i < 12; i++) {
        W[i] = (const float*)d_in[2 + 2 * i];
        B[i] = (const float*)d_in[3 + 2 * i];
    }
    float* bufA; cudaGetSymbolAddress((void**)&bufA, g_bufA);
    float* bufB; cudaGetSymbolAddress((void**)&bufB, g_bufB);
    __half* bufH; cudaGetSymbolAddress((void**)&bufH, g_bufH);
    __half* ah; cudaGetSymbolAddress((void**)&ah, g_ah);
    __half* ah2; cudaGetSymbolAddress((void**)&ah2, g_ah2);
    __half* wth; cudaGetSymbolAddress((void**)&wth, g_wth);
    float* outp = (float*)d_out;

    const int NB = cdiv(NN, 1024);
    k_wconv_all<<<cdiv(32000, 256), 256>>>(W[1], W[2], W[9], W[10]);
    // CSR build
    k_init_cnt<<<cdiv(NN, 256), 256>>>();
    k_count<<<cdiv(NE, 256), 256>>>(dst);
    k_scan1<<<NB, 1024>>>();
    k_scan2<<<1, 128>>>(NB);
    k_scan3<<<NB, 1024>>>();
    k_self<<<cdiv(NN, 256), 256>>>();
    k_edges<<<cdiv(NE, 256), 256>>>(src, dst);

    const int TPB = 256;
    int blocks80 = cdiv(cdiv(NN, 3) * 32, TPB);   // SUB=10, 3 nodes/warp
    int blocks40 = cdiv(cdiv(NN, 6) * 32, TPB);   // SUB=5, 6 nodes/warp
    int blocks4  = cdiv(cdiv(NN, 8) * 32, TPB);   // C=3, 8 nodes/warp
    int blocksN  = cdiv(NN, TPB);

    // encoder
    k_eg1<<<blocks4, TPB>>>(x, W[0], B[0], ah);                                     // agg+eg1 -> fp16
    gemm_h<0, false, 1>(ah, wth + WOFF_EG2, nullptr, bufH, 160, 80);                // eg2 matmul
    k_aggvh<80, 10, 1, true, 1><<<blocks80, TPB>>>(bufH, B[1], nullptr, ah);        // eg2 agg -> fp16
    gemm_h<0, false, 1>(ah, wth + WOFF_EG3, nullptr, bufH, 80, 40);                 // eg3 matmul
    k_aggvh<40, 5, 1, true, 0><<<blocks40, TPB>>>(bufH, B[2], bufB, nullptr);       // eg3 agg
    k_dense<40, 20, 0, false, false><<<blocksN, TPB>>>(bufB, W[3], nullptr, bufA);  // eg4 matmul
    k_aggv<20, 5, 1, true><<<blocks40, TPB>>>(bufA, B[3], bufB);                    // eg4 agg
    // latent dense chain
    k_chain<<<blocksN, TPB>>>(bufB, bufA, W[4], B[4], W[5], B[5], W[6], B[6], W[7], B[7]);
    // decoder
    k_aggv<20, 5, 0, false><<<blocks40, TPB>>>(bufA, nullptr, bufB);                // dg1 agg
    k_dense<20, 40, 1, true, true><<<blocksN, TPB>>>(bufB, W[8], B[8], bufH);       // dg1 -> fp16
    k_aggvh<40, 5, 0, false, 1><<<blocks40, TPB>>>(bufH, nullptr, nullptr, ah);     // dg2 agg -> fp16
    gemm_h<1, true, 1>(ah, wth + WOFF_DG2, B[9], bufH, 40, 80);                     // dg2
    k_aggvh<80, 10, 0, false, 1><<<blocks80, TPB>>>(bufH, nullptr, nullptr, ah);    // dg3 agg -> fp16
    gemm_h<1, true, 1>(ah, wth + WOFF_DG3, B[10], ah2, 80, 160);                    // dg3 -> fp16
    k_dense_h<160, 3, 0, false><<<blocksN, TPB>>>(ah2, W[11], nullptr, bufB);       // dg4 matmul
    k_agg3<2, true, float><<<blocks4, TPB>>>(bufB, B[11], outp);                    // dg4 agg+tanh
}